// round 6
// baseline (speedup 1.0000x reference)
#include <cuda_runtime.h>
#include <cuda_bf16.h>
#include <stdint.h>

typedef unsigned long long ull;

// ---------------------------------------------------------------------------
// Scratch (device globals — no allocation allowed)
// ---------------------------------------------------------------------------
__device__ float g_Wall[128 * 384];   // [Uk | Uq | Wv] fp32
__device__ float g_ball[384];         // [ck+ba1 | cq | bv]
__device__ float g_hkq[2048 * 256];   // [hk | hq]
__device__ float g_c[2048 * 640];     // [v | o0..o3] fp32
__device__ float g_h1[2048 * 256];    // decoder hidden fp32

// ---------------------------------------------------------------------------
// helpers
// ---------------------------------------------------------------------------
__device__ __forceinline__ ull pack2(float lo, float hi) {
    ull r; asm("mov.b64 %0, {%1, %2};" : "=l"(r) : "f"(lo), "f"(hi)); return r;
}
__device__ __forceinline__ void unpack2(ull v, float& lo, float& hi) {
    asm("mov.b64 {%0, %1}, %2;" : "=f"(lo), "=f"(hi) : "l"(v));
}
__device__ __forceinline__ ull fma2(ull a, ull b, ull c) {
    ull d; asm("fma.rn.f32x2 %0, %1, %2, %3;" : "=l"(d) : "l"(a), "l"(b), "l"(c)); return d;
}
__device__ __forceinline__ ull add2(ull a, ull b) {
    ull d; asm("add.rn.f32x2 %0, %1, %2;" : "=l"(d) : "l"(a), "l"(b)); return d;
}
__device__ __forceinline__ float rna_tf32(float x) {
    uint32_t r; asm("cvt.rna.tf32.f32 %0, %1;" : "=r"(r) : "f"(x));
    return __uint_as_float(r);
}
__device__ __forceinline__ void mma_tf32(float c[4],
    uint32_t a0, uint32_t a1, uint32_t a2, uint32_t a3,
    uint32_t b0, uint32_t b1)
{
    asm("mma.sync.aligned.m16n8k8.row.col.f32.tf32.tf32.f32 "
        "{%0,%1,%2,%3},{%4,%5,%6,%7},{%8,%9},{%0,%1,%2,%3};"
        : "+f"(c[0]), "+f"(c[1]), "+f"(c[2]), "+f"(c[3])
        : "r"(a0), "r"(a1), "r"(a2), "r"(a3), "r"(b0), "r"(b1));
}
__device__ __forceinline__ uint32_t fu(float x) { return __float_as_uint(x); }

// MUFU-free sigmoid: exp2 via bit tricks + Newton reciprocal.
// Seed for 1/d on d in (1,2]: r0 = 24/17 - (8/17)*d  (max rel err 1/17).
__device__ __forceinline__ float sigmoid_fma(float s) {
    float t = s * 1.4426950408889634f;
    float tn = -fabsf(t);
    tn = fmaxf(tn, -125.0f);
    float m = tn + 12582912.0f;             // round-to-nearest-even int
    int ib = __float_as_int(m);
    float n = m - 12582912.0f;
    float f = tn - n;                        // f in [-0.5, 0.5]
    float p = 1.33335581e-3f;
    p = fmaf(p, f, 9.61812910e-3f);
    p = fmaf(p, f, 5.55041087e-2f);
    p = fmaf(p, f, 2.40226507e-1f);
    p = fmaf(p, f, 6.93147181e-1f);
    p = fmaf(p, f, 1.0f);
    float scale = __int_as_float((ib - 0x4B400000 + 127) << 23);
    float e = p * scale;                     // exp(-|s|)  in (0, 1]
    float d = 1.0f + e;                      // in (1, 2]
    float r = fmaf(d, -0.47058824f, 1.41176471f);  // FIXED seed for (1,2]
    r = r * fmaf(-d, r, 2.0f);
    r = r * fmaf(-d, r, 2.0f);
    r = r * fmaf(-d, r, 2.0f);               // rel err ~1e-10
    float sn = e * r;                        // sigmoid(-|s|)
    return (s > 0.0f) ? (1.0f - sn) : sn;
}

// ---------------------------------------------------------------------------
// prep: fused [Uk|Uq|Wv] (fp32) + fused bias.
// ---------------------------------------------------------------------------
__global__ __launch_bounds__(256) void prep_kernel(
    const float* __restrict__ Wk, const float* __restrict__ bk,
    const float* __restrict__ Wq, const float* __restrict__ bq,
    const float* __restrict__ Wv, const float* __restrict__ bv,
    const float* __restrict__ Wa1, const float* __restrict__ ba1)
{
    __shared__ float wa[64 * 32];
    int tid = threadIdx.x;
    for (int i = tid; i < 64 * 32; i += 256) wa[i] = Wa1[i];
    __syncthreads();

    int stride = gridDim.x * 256;
    for (int idx = blockIdx.x * 256 + tid; idx < 128 * 128; idx += stride) {
        int d = idx >> 7, j = idx & 127;
        int hb = j & ~31, a = j & 31;
        float sk = 0.f, sq = 0.f;
        #pragma unroll
        for (int t = 0; t < 32; t++) {
            sk += Wk[d * 128 + hb + t] * wa[t * 32 + a];
            sq += Wq[d * 128 + hb + t] * wa[(32 + t) * 32 + a];
        }
        g_Wall[d * 384 + j]       = sk;
        g_Wall[d * 384 + 128 + j] = sq;
        g_Wall[d * 384 + 256 + j] = Wv[d * 128 + j];
    }
    if (blockIdx.x == 0 && tid < 128) {
        int hb = tid & ~31, a = tid & 31;
        float sk = 0.f, sq = 0.f;
        #pragma unroll
        for (int t = 0; t < 32; t++) {
            sk += bk[hb + t] * wa[t * 32 + a];
            sq += bq[hb + t] * wa[(32 + t) * 32 + a];
        }
        g_ball[tid]       = sk + ba1[a];
        g_ball[128 + tid] = sq;
        g_ball[256 + tid] = bv[tid];
    }
}

// ---------------------------------------------------------------------------
// 3xTF32 GEMM: C = act(A @ W + bias), near-fp32 accuracy.
// Tile 64x64, K-chunk 32, 256 threads (8 warps: 2m x 4n).
// A, W split hi/lo at STS time; 3 mma passes: hi*hi + lo*hi + hi*lo.
// Loader: per thread 4 x LDG.32 (k, k+8, k+16, k+24) -> one STS.128 to the
// k-permuted row (perm col of k = ((k&7)<<2)|(k>>3); the 4 loads land in one
// contiguous float4 at column (k&7)*4).
// ---------------------------------------------------------------------------
template <bool RELU>
__global__ __launch_bounds__(256, 2) void gemm3x(
    const float* __restrict__ A, int lda,
    const float* __restrict__ W, int ldw,
    const float* __restrict__ bias,
    float* __restrict__ C1, int ldc1,
    float* __restrict__ C2, int ldc2, int nsplit,
    int K)
{
    __shared__ float AsH[64][36], AsL[64][36];
    __shared__ float BsH[64][36], BsL[64][36];

    int tid = threadIdx.x;
    int lane = tid & 31, wq = tid >> 5;
    int wm = wq >> 2, wn = wq & 3;
    int r = lane >> 2, c4 = lane & 3;
    int m0 = blockIdx.y * 64, n0 = blockIdx.x * 64;

    float acc[2][2][4];
    #pragma unroll
    for (int i = 0; i < 2; i++)
        #pragma unroll
        for (int j = 0; j < 2; j++)
            #pragma unroll
            for (int e = 0; e < 4; e++) acc[i][j][e] = 0.f;

    int nch = K >> 5;

    // per-thread load slots (lin spans 0..511 over the two slots)
    int am[2], ak0[2], bn[2], bk0[2];
    #pragma unroll
    for (int s = 0; s < 2; s++) {
        int lin = tid + s * 256;
        am[s] = lin >> 3;  ak0[s] = lin & 7;   // A: 64m x 8 k-groups
        bn[s] = lin & 63;  bk0[s] = lin >> 6;  // B: 64n x 8 k-groups
    }

    float rA[2][4], rB[2][4];
    auto ldg_chunk = [&](int kc) {
        #pragma unroll
        for (int s = 0; s < 2; s++)
            #pragma unroll
            for (int u = 0; u < 4; u++) {
                rA[s][u] = A[(size_t)(m0 + am[s]) * lda + kc + ak0[s] + 8 * u];
                rB[s][u] = W[(size_t)(kc + bk0[s] + 8 * u) * ldw + n0 + bn[s]];
            }
    };
    ldg_chunk(0);

    for (int ck = 0; ck < nch; ck++) {
        __syncthreads();   // prev chunk's fragment LDS done everywhere
        #pragma unroll
        for (int s = 0; s < 2; s++) {
            float4 h, l;
            h.x = rna_tf32(rA[s][0]); h.y = rna_tf32(rA[s][1]);
            h.z = rna_tf32(rA[s][2]); h.w = rna_tf32(rA[s][3]);
            l.x = rA[s][0] - h.x; l.y = rA[s][1] - h.y;
            l.z = rA[s][2] - h.z; l.w = rA[s][3] - h.w;
            *(float4*)&AsH[am[s]][ak0[s] * 4] = h;
            *(float4*)&AsL[am[s]][ak0[s] * 4] = l;
            h.x = rna_tf32(rB[s][0]); h.y = rna_tf32(rB[s][1]);
            h.z = rna_tf32(rB[s][2]); h.w = rna_tf32(rB[s][3]);
            l.x = rB[s][0] - h.x; l.y = rB[s][1] - h.y;
            l.z = rB[s][2] - h.z; l.w = rB[s][3] - h.w;
            *(float4*)&BsH[bn[s]][bk0[s] * 4] = h;
            *(float4*)&BsL[bn[s]][bk0[s] * 4] = l;
        }
        __syncthreads();
        if (ck + 1 < nch) ldg_chunk((ck + 1) << 5);

        // B fragments (hoisted)
        float4 bH0[2], bH1[2], bL0[2], bL1[2];
        #pragma unroll
        for (int nt = 0; nt < 2; nt++) {
            int nb = wn * 16 + nt * 8 + r;
            bH0[nt] = *(const float4*)&BsH[nb][c4 * 4];
            bH1[nt] = *(const float4*)&BsH[nb][(c4 + 4) * 4];
            bL0[nt] = *(const float4*)&BsL[nb][c4 * 4];
            bL1[nt] = *(const float4*)&BsL[nb][(c4 + 4) * 4];
        }
        #pragma unroll
        for (int mt = 0; mt < 2; mt++) {
            int rb = wm * 32 + mt * 16 + r;
            float4 aH[4], aL[4];
            aH[0] = *(const float4*)&AsH[rb][c4 * 4];
            aH[1] = *(const float4*)&AsH[rb + 8][c4 * 4];
            aH[2] = *(const float4*)&AsH[rb][(c4 + 4) * 4];
            aH[3] = *(const float4*)&AsH[rb + 8][(c4 + 4) * 4];
            aL[0] = *(const float4*)&AsL[rb][c4 * 4];
            aL[1] = *(const float4*)&AsL[rb + 8][c4 * 4];
            aL[2] = *(const float4*)&AsL[rb][(c4 + 4) * 4];
            aL[3] = *(const float4*)&AsL[rb + 8][(c4 + 4) * 4];
            #pragma unroll
            for (int kt = 0; kt < 4; kt++) {
                float ah0 = ((const float*)&aH[0])[kt], ah1 = ((const float*)&aH[1])[kt];
                float ah2 = ((const float*)&aH[2])[kt], ah3 = ((const float*)&aH[3])[kt];
                float al0 = ((const float*)&aL[0])[kt], al1 = ((const float*)&aL[1])[kt];
                float al2 = ((const float*)&aL[2])[kt], al3 = ((const float*)&aL[3])[kt];
                #pragma unroll
                for (int nt = 0; nt < 2; nt++) {
                    float bh0 = ((const float*)&bH0[nt])[kt], bh1 = ((const float*)&bH1[nt])[kt];
                    float bl0 = ((const float*)&bL0[nt])[kt], bl1 = ((const float*)&bL1[nt])[kt];
                    mma_tf32(acc[mt][nt], fu(ah0), fu(ah1), fu(ah2), fu(ah3), fu(bh0), fu(bh1));
                    mma_tf32(acc[mt][nt], fu(al0), fu(al1), fu(al2), fu(al3), fu(bh0), fu(bh1));
                    mma_tf32(acc[mt][nt], fu(ah0), fu(ah1), fu(ah2), fu(ah3), fu(bl0), fu(bl1));
                }
            }
        }
    }

    bool left = (n0 < nsplit);
    float* Cb = left ? (C1 + n0) : (C2 + (n0 - nsplit));
    int ldc = left ? ldc1 : ldc2;

    #pragma unroll
    for (int mt = 0; mt < 2; mt++) {
        #pragma unroll
        for (int nt = 0; nt < 2; nt++) {
            int row = m0 + wm * 32 + mt * 16 + r;
            int col = wn * 16 + nt * 8 + 2 * c4;
            float2 bb = *(const float2*)(bias + n0 + col);
            float o0 = acc[mt][nt][0] + bb.x, o1 = acc[mt][nt][1] + bb.y;
            float o2 = acc[mt][nt][2] + bb.x, o3 = acc[mt][nt][3] + bb.y;
            if (RELU) {
                o0 = fmaxf(o0, 0.f); o1 = fmaxf(o1, 0.f);
                o2 = fmaxf(o2, 0.f); o3 = fmaxf(o3, 0.f);
            }
            *(float2*)(Cb + (size_t)row * ldc + col) = make_float2(o0, o1);
            *(float2*)(Cb + (size_t)(row + 8) * ldc + col) = make_float2(o2, o3);
        }
    }
}

// ---------------------------------------------------------------------------
// Attention. Block = (32 i-rows, head, batch), grid (32,4,2) = 256 blocks.
// fp32 f32x2 scores + FMA sigmoid; wv via 3-pass tf32 mma (w hi/lo, v hi + bf16 lo).
// Double-buffered v and hq, 2 syncs per j-tile.
// Dynamic smem layout (bytes):
//   vH : [2][32][136] f32   0      .. 34816
//   vL : [2][32][136] bf16  34816  .. 52224
//   hq : [2][32][36]  f32   52224  .. 61440
//   hk : [32][36]     f32   61440  .. 66048
//   wH : [32][36]     f32   66048  .. 70656
//   wL : [32][36]     f32   70656  .. 75264
//   wa2p: [16] ull          75264  .. 75392
// ---------------------------------------------------------------------------
#define ATTN_SMEM 75392

__global__ __launch_bounds__(256, 2) void attn_kernel(
    const float* __restrict__ hkq,
    float* __restrict__ cbuf,
    const float* __restrict__ Wa2,
    const float* __restrict__ ba2)
{
    extern __shared__ char smem[];
    float* vH = (float*)smem;                                  // [2][32][136]
    __nv_bfloat16* vL = (__nv_bfloat16*)(smem + 34816);        // [2][32][136]
    float* hq_s = (float*)(smem + 52224);                      // [2][32][36]
    float* hk_s = (float*)(smem + 61440);                      // [32][36]
    float* wH = (float*)(smem + 66048);                        // [32][36]
    float* wL = (float*)(smem + 70656);                        // [32][36]
    ull* wa2p = (ull*)(smem + 75264);                          // [16]

    int tid = threadIdx.x;
    int lane = tid & 31, wq = tid >> 5;
    int tx = tid & 15, ty = tid >> 4;
    int it = blockIdx.x, head = blockIdx.y, bb = blockIdx.z;
    int mbase = bb * 1024 + it * 32;

    if (tid < 16) {
        float w0 = 0.5f * Wa2[2 * tid], w1 = 0.5f * Wa2[2 * tid + 1];
        wa2p[tid] = pack2(w0, w1);
    }
    {   // hk tile (resident)
        int i = tid & 31, a4 = tid >> 5;
        float4 f = *(const float4*)(hkq + (size_t)(mbase + i) * 256 + head * 32 + a4 * 4);
        *(float4*)&hk_s[i * 36 + a4 * 4] = f;
    }
    {   // jt=0: hq + v into buffer 0
        int j = tid & 31, a4 = tid >> 5;
        float4 f = *(const float4*)(hkq + (size_t)(bb * 1024 + j) * 256 + 128 + head * 32 + a4 * 4);
        *(float4*)&hq_s[j * 36 + a4 * 4] = f;
        #pragma unroll
        for (int s = 0; s < 4; s++) {
            int lin = tid + s * 256;
            int jj = lin >> 5, d4 = lin & 31;
            float4 g = *(const float4*)(cbuf + (size_t)(bb * 1024 + jj) * 640 + d4 * 4);
            float4 h; h.x = rna_tf32(g.x); h.y = rna_tf32(g.y);
            h.z = rna_tf32(g.z); h.w = rna_tf32(g.w);
            *(float4*)&vH[jj * 136 + d4 * 4] = h;
            __nv_bfloat16* dst = &vL[jj * 136 + d4 * 4];
            dst[0] = __float2bfloat16(g.x - h.x);
            dst[1] = __float2bfloat16(g.y - h.y);
            dst[2] = __float2bfloat16(g.z - h.z);
            dst[3] = __float2bfloat16(g.w - h.w);
        }
    }
    __syncthreads();

    float ba2v = ba2[0];
    float acc[2][2][4];
    #pragma unroll
    for (int i = 0; i < 2; i++)
        #pragma unroll
        for (int j = 0; j < 2; j++)
            #pragma unroll
            for (int e = 0; e < 4; e++) acc[i][j][e] = 0.f;

    int i0 = ty * 2, j0 = tx * 2;
    const ull ABSM = 0x7FFFFFFF7FFFFFFFULL;

    for (int jt = 0; jt < 32; jt++) {
        int p = jt & 1;
        const float* vHp = vH + p * 32 * 136;
        const __nv_bfloat16* vLp = vL + p * 32 * 136;
        const float* hqp = hq_s + p * 32 * 36;

        // prefetch next tile to regs
        float4 nhq; float4 nv[4];
        if (jt < 31) {
            int jn = bb * 1024 + (jt + 1) * 32;
            nhq = *(const float4*)(hkq + (size_t)(jn + (tid & 31)) * 256 + 128 + head * 32 + (tid >> 5) * 4);
            #pragma unroll
            for (int s = 0; s < 4; s++) {
                int lin = tid + s * 256;
                nv[s] = *(const float4*)(cbuf + (size_t)(jn + (lin >> 5)) * 640 + (lin & 31) * 4);
            }
        }

        // ---- scores (2i x 2j), f32x2, exact identity relu(u)*w = (u+|u|)*(w/2)
        ull s2[4][2];
        #pragma unroll
        for (int c = 0; c < 4; c++) { s2[c][0] = 0ULL; s2[c][1] = 0ULL; }
        #pragma unroll
        for (int a4 = 0; a4 < 8; a4++) {
            float4 kA = *(const float4*)&hk_s[i0 * 36 + a4 * 4];
            float4 kB = *(const float4*)&hk_s[(i0 + 1) * 36 + a4 * 4];
            float4 qA = *(const float4*)&hqp[j0 * 36 + a4 * 4];
            float4 qB = *(const float4*)&hqp[(j0 + 1) * 36 + a4 * 4];
            ull whp0 = wa2p[a4 * 2], whp1 = wa2p[a4 * 2 + 1];
            ull kA0 = pack2(kA.x, kA.y), kA1 = pack2(kA.z, kA.w);
            ull kB0 = pack2(kB.x, kB.y), kB1 = pack2(kB.z, kB.w);
            ull qA0 = pack2(qA.x, qA.y), qA1 = pack2(qA.z, qA.w);
            ull qB0 = pack2(qB.x, qB.y), qB1 = pack2(qB.z, qB.w);
            #define SCOMBO(kp0, kp1, qp0, qp1, c) { \
                ull u0 = add2(kp0, qp0), u1 = add2(kp1, qp1); \
                ull t0 = add2(u0, u0 & ABSM); \
                ull t1 = add2(u1, u1 & ABSM); \
                s2[c][0] = fma2(t0, whp0, s2[c][0]); \
                s2[c][1] = fma2(t1, whp1, s2[c][1]); }
            SCOMBO(kA0, kA1, qA0, qA1, 0)
            SCOMBO(kA0, kA1, qB0, qB1, 1)
            SCOMBO(kB0, kB1, qA0, qA1, 2)
            SCOMBO(kB0, kB1, qB0, qB1, 3)
            #undef SCOMBO
        }
        float sc[4];
        #pragma unroll
        for (int c = 0; c < 4; c++) {
            float f0, f1, f2, f3;
            unpack2(s2[c][0], f0, f1);
            unpack2(s2[c][1], f2, f3);
            sc[c] = ba2v + ((f0 + f1) + (f2 + f3));
        }
        if (it * 32 + i0 == jt * 32 + j0) { sc[0] -= 10000.f; sc[3] -= 10000.f; }

        float wv[4];
        #pragma unroll
        for (int c = 0; c < 4; c++) wv[c] = sigmoid_fma(sc[c]);

        __syncthreads();   // prev mma done (wH/wL free), scores done (hq[1-p] free)

        // store w (split hi/lo) at permuted column
        #pragma unroll
        for (int c = 0; c < 4; c++) {
            int ii = i0 + (c >> 1), jj = j0 + (c & 1);
            int pj = ((jj & 7) << 2) | (jj >> 3);
            float h = rna_tf32(wv[c]);
            wH[ii * 36 + pj] = h;
            wL[ii * 36 + pj] = wv[c] - h;
        }
        // store prefetched tiles into buffers [1-p]
        if (jt < 31) {
            float* vHn = vH + (1 - p) * 32 * 136;
            __nv_bfloat16* vLn = vL + (1 - p) * 32 * 136;
            float* hqn = hq_s + (1 - p) * 32 * 36;
            *(float4*)&hqn[(tid & 31) * 36 + (tid >> 5) * 4] = nhq;
            #pragma unroll
            for (int s = 0; s < 4; s++) {
                int lin = tid + s * 256;
                int jj = lin >> 5, d4 = lin & 31;
                float4 g = nv[s];
                float4 h; h.x = rna_tf32(g.x); h.y = rna_tf32(g.y);
                h.z = rna_tf32(g.z); h.w = rna_tf32(g.w);
                *(float4*)&vHn[jj * 136 + d4 * 4] = h;
                __nv_bfloat16* dst = &vLn[jj * 136 + d4 * 4];
                dst[0] = __float2bfloat16(g.x - h.x);
                dst[1] = __float2bfloat16(g.y - h.y);
                dst[2] = __float2bfloat16(g.z - h.z);
                dst[3] = __float2bfloat16(g.w - h.w);
            }
        }
        __syncthreads();   // wH/wL + v[p] ready for mma

        // ---- wv mma, 3 passes: wH*vH + wL*vH + wH*vL. warp wq owns d 16-cols.
        {
            int r = lane >> 2, c4 = lane & 3;
            int n0 = wq * 16;
            float4 aH[4], aL[4];
            #pragma unroll
            for (int mt = 0; mt < 2; mt++) {
                aH[mt * 2 + 0] = *(const float4*)&wH[(mt * 16 + r) * 36 + c4 * 4];
                aH[mt * 2 + 1] = *(const float4*)&wH[(mt * 16 + 8 + r) * 36 + c4 * 4];
                aL[mt * 2 + 0] = *(const float4*)&wL[(mt * 16 + r) * 36 + c4 * 4];
                aL[mt * 2 + 1] = *(const float4*)&wL[(mt * 16 + 8 + r) * 36 + c4 * 4];
            }
            float4 aH2[4], aL2[4];
            #pragma unroll
            for (int mt = 0; mt < 2; mt++) {
                aH2[mt * 2 + 0] = *(const float4*)&wH[(mt * 16 + r) * 36 + (c4 + 4) * 4];
                aH2[mt * 2 + 1] = *(const float4*)&wH[(mt * 16 + 8 + r) * 36 + (c4 + 4) * 4];
                aL2[mt * 2 + 0] = *(const float4*)&wL[(mt * 16 + r) * 36 + (c4 + 4) * 4];
                aL2[mt * 2 + 1] = *(const float4*)&wL[(mt * 16 + 8 + r) * 36 + (c4 + 4) * 4];
            }
            #pragma unroll
            for (int kt = 0; kt < 4; kt++) {
                #pragma unroll
                for (int nt = 0; nt < 2; nt++) {
                    int col = n0 + nt * 8 + r;
                    float bh0 = vHp[(kt * 8 + c4) * 136 + col];
                    float bh1 = vHp[(kt * 8 + c4 + 4) * 136 + col];
                    float bl0 = __bfloat162float(vLp[(kt * 8 + c4) * 136 + col]);
                    float bl1 = __bfloat162float(vLp[(kt * 8 + c4 + 4) * 136 + col]);
                    #pragma unroll
                    for (int mt = 0; mt < 2; mt++) {
                        float h0 = ((const float*)&aH[mt * 2 + 0])[kt];
                        float h1 = ((const float*)&aH[mt * 2 + 1])[kt];
                        float h2 = ((const float*)&aH2[mt * 2 + 0])[kt];
                        float h3 = ((const float*)&aH2[mt * 2 + 1])[kt];
                        float l0 = ((const float*)&aL[mt * 2 + 0])[kt];
                        float l1 = ((const float*)&aL[mt * 2 + 1])[kt];
                        float l2 = ((const float*)&aL2[mt * 2 + 0])[kt];
                        float l3 = ((const float*)&aL2[mt * 2 + 1])[kt];
                        mma_tf32(acc[mt][nt], fu(h0), fu(h1), fu(h2), fu(h3), fu(bh0), fu(bh1));
                        mma_tf32(acc[mt][nt], fu(l0), fu(l1), fu(l2), fu(l3), fu(bh0), fu(bh1));
                        mma_tf32(acc[mt][nt], fu(h0), fu(h1), fu(h2), fu(h3), fu(bl0), fu(bl1));
                    }
                }
            }
        }
    }

    // epilogue: fp32 out
    {
        int r = lane >> 2, c4 = lane & 3;
        #pragma unroll
        for (int mt = 0; mt < 2; mt++) {
            #pragma unroll
            for (int nt = 0; nt < 2; nt++) {
                int row = mbase + mt * 16 + r;
                int col = 128 + head * 128 + wq * 16 + nt * 8 + 2 * c4;
                *(float2*)(cbuf + (size_t)row * 640 + col) =
                    make_float2(acc[mt][nt][0], acc[mt][nt][1]);
                *(float2*)(cbuf + (size_t)(row + 8) * 640 + col) =
                    make_float2(acc[mt][nt][2], acc[mt][nt][3]);
            }
        }
    }
}

// ---------------------------------------------------------------------------
// launch
// ---------------------------------------------------------------------------
extern "C" void kernel_launch(void* const* d_in, const int* in_sizes, int n_in,
                              void* d_out, int out_size)
{
    const float* x   = (const float*)d_in[0];
    const float* Wk  = (const float*)d_in[1];
    const float* bk  = (const float*)d_in[2];
    const float* Wq  = (const float*)d_in[3];
    const float* bq  = (const float*)d_in[4];
    const float* Wv  = (const float*)d_in[5];
    const float* bv  = (const float*)d_in[6];
    const float* Wa1 = (const float*)d_in[7];
    const float* ba1 = (const float*)d_in[8];
    const float* Wa2 = (const float*)d_in[9];
    const float* ba2 = (const float*)d_in[10];
    const float* Wd1 = (const float*)d_in[11];
    const float* bd1 = (const float*)d_in[12];
    const float* Wd2 = (const float*)d_in[13];
    const float* bd2 = (const float*)d_in[14];
    float* out = (float*)d_out;

    float *pWall, *pball, *phkq, *pc, *ph1;
    cudaGetSymbolAddress((void**)&pWall, g_Wall);
    cudaGetSymbolAddress((void**)&pball, g_ball);
    cudaGetSymbolAddress((void**)&phkq, g_hkq);
    cudaGetSymbolAddress((void**)&pc,   g_c);
    cudaGetSymbolAddress((void**)&ph1,  g_h1);

    cudaFuncSetAttribute(attn_kernel,
                         cudaFuncAttributeMaxDynamicSharedMemorySize, ATTN_SMEM);

    // 1. fused effective weights + biases
    prep_kernel<<<16, 256>>>(Wk, bk, Wq, bq, Wv, bv, Wa1, ba1);

    // 2. [hk|hq|v] = x @ Wall + ball   (M=2048, N=384, K=128)
    gemm3x<false><<<dim3(6, 32), 256>>>(x, 128, pWall, 384, pball,
                                        phkq, 256, pc, 640, 256, 128);

    // 3. attention: writes g_c cols [128, 640)
    attn_kernel<<<dim3(32, 4, 2), 256, ATTN_SMEM>>>(phkq, pc, Wa2, ba2);

    // 4. h1 = relu(c @ Wd1 + bd1)      (M=2048, N=256, K=640)
    gemm3x<true><<<dim3(4, 32), 256>>>(pc, 640, Wd1, 256, bd1,
                                       ph1, 256, ph1, 256, 1 << 30, 640);

    // 5. out = h1 @ Wd2 + bd2          (M=2048, N=128, K=256)
    gemm3x<false><<<dim3(2, 32), 256>>>(ph1, 256, Wd2, 128, bd2,
                                        out, 128, out, 128, 1 << 30, 256);
}

// round 7
// speedup vs baseline: 1.1282x; 1.1282x over previous
#include <cuda_runtime.h>
#include <stdint.h>

typedef unsigned long long ull;

// ---------------------------------------------------------------------------
// Scratch (device globals — no allocation allowed)
// ---------------------------------------------------------------------------
__device__ float g_Wall[128 * 384];   // [Uk | Uq | Wv] fp32
__device__ float g_ball[384];         // [ck+ba1 | cq | bv]
__device__ float g_hkq[2048 * 256];   // [hk | hq]
__device__ float g_dots[2048 * 8];    // per row: [kdot h0..h3 (incl ba2) | qdot h0..h3]
__device__ float g_c[2048 * 640];     // [v | o0..o3] fp32
__device__ float g_h1[2048 * 256];    // decoder hidden fp32

// ---------------------------------------------------------------------------
// helpers
// ---------------------------------------------------------------------------
__device__ __forceinline__ ull pack2(float lo, float hi) {
    ull r; asm("mov.b64 %0, {%1, %2};" : "=l"(r) : "f"(lo), "f"(hi)); return r;
}
__device__ __forceinline__ void unpack2(ull v, float& lo, float& hi) {
    asm("mov.b64 {%0, %1}, %2;" : "=f"(lo), "=f"(hi) : "l"(v));
}
__device__ __forceinline__ ull fma2(ull a, ull b, ull c) {
    ull d; asm("fma.rn.f32x2 %0, %1, %2, %3;" : "=l"(d) : "l"(a), "l"(b), "l"(c)); return d;
}
__device__ __forceinline__ ull add2(ull a, ull b) {
    ull d; asm("add.rn.f32x2 %0, %1, %2;" : "=l"(d) : "l"(a), "l"(b)); return d;
}
__device__ __forceinline__ float rna_tf32(float x) {
    uint32_t r; asm("cvt.rna.tf32.f32 %0, %1;" : "=r"(r) : "f"(x));
    return __uint_as_float(r);
}
__device__ __forceinline__ void mma_tf32(float c[4],
    uint32_t a0, uint32_t a1, uint32_t a2, uint32_t a3,
    uint32_t b0, uint32_t b1)
{
    asm("mma.sync.aligned.m16n8k8.row.col.f32.tf32.tf32.f32 "
        "{%0,%1,%2,%3},{%4,%5,%6,%7},{%8,%9},{%0,%1,%2,%3};"
        : "+f"(c[0]), "+f"(c[1]), "+f"(c[2]), "+f"(c[3])
        : "r"(a0), "r"(a1), "r"(a2), "r"(a3), "r"(b0), "r"(b1));
}
__device__ __forceinline__ uint32_t fu(float x) { return __float_as_uint(x); }

// MUFU-free sigmoid (2 Newton iters, rel err ~1e-5 — plenty).
__device__ __forceinline__ float sigmoid_fma(float s) {
    float t = s * 1.4426950408889634f;
    float tn = -fabsf(t);
    tn = fmaxf(tn, -125.0f);
    float m = tn + 12582912.0f;
    int ib = __float_as_int(m);
    float n = m - 12582912.0f;
    float f = tn - n;
    float p = 1.33335581e-3f;
    p = fmaf(p, f, 9.61812910e-3f);
    p = fmaf(p, f, 5.55041087e-2f);
    p = fmaf(p, f, 2.40226507e-1f);
    p = fmaf(p, f, 6.93147181e-1f);
    p = fmaf(p, f, 1.0f);
    float scale = __int_as_float((ib - 0x4B400000 + 127) << 23);
    float e = p * scale;                     // exp(-|s|) in (0,1]
    float d = 1.0f + e;                      // in (1,2]
    float r = fmaf(d, -0.47058824f, 1.41176471f);  // seed valid on (1,2]
    r = r * fmaf(-d, r, 2.0f);
    r = r * fmaf(-d, r, 2.0f);
    float sn = e * r;
    return (s > 0.0f) ? (1.0f - sn) : sn;
}

// ---------------------------------------------------------------------------
// prep: fused [Uk|Uq|Wv] (fp32) + fused bias (ba1 folded into hk bias).
// ---------------------------------------------------------------------------
__global__ __launch_bounds__(256) void prep_kernel(
    const float* __restrict__ Wk, const float* __restrict__ bk,
    const float* __restrict__ Wq, const float* __restrict__ bq,
    const float* __restrict__ Wv, const float* __restrict__ bv,
    const float* __restrict__ Wa1, const float* __restrict__ ba1)
{
    __shared__ float wa[64 * 32];
    int tid = threadIdx.x;
    for (int i = tid; i < 64 * 32; i += 256) wa[i] = Wa1[i];
    __syncthreads();

    int stride = gridDim.x * 256;
    for (int idx = blockIdx.x * 256 + tid; idx < 128 * 128; idx += stride) {
        int d = idx >> 7, j = idx & 127;
        int hb = j & ~31, a = j & 31;
        float sk = 0.f, sq = 0.f;
        #pragma unroll
        for (int t = 0; t < 32; t++) {
            sk += Wk[d * 128 + hb + t] * wa[t * 32 + a];
            sq += Wq[d * 128 + hb + t] * wa[(32 + t) * 32 + a];
        }
        g_Wall[d * 384 + j]       = sk;
        g_Wall[d * 384 + 128 + j] = sq;
        g_Wall[d * 384 + 256 + j] = Wv[d * 128 + j];
    }
    if (blockIdx.x == 0 && tid < 128) {
        int hb = tid & ~31, a = tid & 31;
        float sk = 0.f, sq = 0.f;
        #pragma unroll
        for (int t = 0; t < 32; t++) {
            sk += bk[hb + t] * wa[t * 32 + a];
            sq += bq[hb + t] * wa[(32 + t) * 32 + a];
        }
        g_ball[tid]       = sk + ba1[a];
        g_ball[128 + tid] = sq;
        g_ball[256 + tid] = bv[tid];
    }
}

// ---------------------------------------------------------------------------
// dots: per (row, head): kdot = ba2 + sum_a hk[row,h,a]*Wa2[a]/2
//                        qdot =       sum_a hq[row,h,a]*Wa2[a]/2
// layout: g_dots[row*8 + isq*4 + head]
// ---------------------------------------------------------------------------
__global__ __launch_bounds__(256) void dots_kernel(
    const float* __restrict__ hkq, const float* __restrict__ Wa2,
    const float* __restrict__ ba2)
{
    int idx = blockIdx.x * 256 + threadIdx.x;   // 2048*8 = 16384
    if (idx >= 2048 * 8) return;
    int row = idx >> 3, r = idx & 7;
    int isq = r >> 2, h = r & 3;
    const float* base = hkq + (size_t)row * 256 + isq * 128 + h * 32;
    float s = 0.f;
    #pragma unroll
    for (int a = 0; a < 32; a++) s += base[a] * (0.5f * Wa2[a]);
    if (!isq) s += ba2[0];
    g_dots[idx] = s;
}

// ---------------------------------------------------------------------------
// 2-pass TF32 GEMM: C = act(A @ W + bias).  A split hi/lo (exact), W rounded
// once -> error ~1.4e-4 RMS.  Tile 64x64, K-chunk 32, 256 threads, smem
// double-buffered (1 sync/chunk).  Column router as before.
// Dynamic smem: AsH[2][2304] | AsL[2][2304] | Bs[2][2304] = 55296 B.
// ---------------------------------------------------------------------------
#define GEMM_SMEM 55296

template <bool RELU>
__global__ __launch_bounds__(256, 2) void gemm2x(
    const float* __restrict__ A, int lda,
    const float* __restrict__ W, int ldw,
    const float* __restrict__ bias,
    float* __restrict__ C1, int ldc1,
    float* __restrict__ C2, int ldc2, int nsplit,
    int K)
{
    extern __shared__ float sm[];
    float* AsH = sm;            // [2][64*36]
    float* AsL = sm + 4608;
    float* Bs  = sm + 9216;

    int tid = threadIdx.x;
    int lane = tid & 31, wq = tid >> 5;
    int wm = wq >> 2, wn = wq & 3;
    int r = lane >> 2, c4 = lane & 3;
    int m0 = blockIdx.y * 64, n0 = blockIdx.x * 64;

    float acc[2][2][4];
    #pragma unroll
    for (int i = 0; i < 2; i++)
        #pragma unroll
        for (int j = 0; j < 2; j++)
            #pragma unroll
            for (int e = 0; e < 4; e++) acc[i][j][e] = 0.f;

    int nch = K >> 5;

    int am[2], ak0[2], bn[2], bk0[2];
    #pragma unroll
    for (int s = 0; s < 2; s++) {
        int lin = tid + s * 256;
        am[s] = lin >> 3;  ak0[s] = lin & 7;
        bn[s] = lin & 63;  bk0[s] = lin >> 6;
    }

    float rA[2][4], rB[2][4];
    auto ldg_chunk = [&](int kc) {
        #pragma unroll
        for (int s = 0; s < 2; s++)
            #pragma unroll
            for (int u = 0; u < 4; u++) {
                rA[s][u] = A[(size_t)(m0 + am[s]) * lda + kc + ak0[s] + 8 * u];
                rB[s][u] = W[(size_t)(kc + bk0[s] + 8 * u) * ldw + n0 + bn[s]];
            }
    };
    auto store_chunk = [&](int buf) {
        float* aH = AsH + buf * 2304;
        float* aL = AsL + buf * 2304;
        float* bs = Bs  + buf * 2304;
        #pragma unroll
        for (int s = 0; s < 2; s++) {
            float4 h, l;
            h.x = rna_tf32(rA[s][0]); h.y = rna_tf32(rA[s][1]);
            h.z = rna_tf32(rA[s][2]); h.w = rna_tf32(rA[s][3]);
            l.x = rA[s][0] - h.x; l.y = rA[s][1] - h.y;
            l.z = rA[s][2] - h.z; l.w = rA[s][3] - h.w;
            *(float4*)&aH[am[s] * 36 + ak0[s] * 4] = h;
            *(float4*)&aL[am[s] * 36 + ak0[s] * 4] = l;
            float4 b;
            b.x = rna_tf32(rB[s][0]); b.y = rna_tf32(rB[s][1]);
            b.z = rna_tf32(rB[s][2]); b.w = rna_tf32(rB[s][3]);
            *(float4*)&bs[bn[s] * 36 + bk0[s] * 4] = b;
        }
    };

    ldg_chunk(0);
    store_chunk(0);
    __syncthreads();

    for (int ck = 0; ck < nch; ck++) {
        int p = ck & 1;
        if (ck + 1 < nch) ldg_chunk((ck + 1) << 5);

        const float* aHp = AsH + p * 2304;
        const float* aLp = AsL + p * 2304;
        const float* bsp = Bs  + p * 2304;

        float4 bH0[2], bH1[2];
        #pragma unroll
        for (int nt = 0; nt < 2; nt++) {
            int nb = wn * 16 + nt * 8 + r;
            bH0[nt] = *(const float4*)&bsp[nb * 36 + c4 * 4];
            bH1[nt] = *(const float4*)&bsp[nb * 36 + (c4 + 4) * 4];
        }
        #pragma unroll
        for (int mt = 0; mt < 2; mt++) {
            int rb = wm * 32 + mt * 16 + r;
            float4 aH[4], aL[4];
            aH[0] = *(const float4*)&aHp[rb * 36 + c4 * 4];
            aH[1] = *(const float4*)&aHp[(rb + 8) * 36 + c4 * 4];
            aH[2] = *(const float4*)&aHp[rb * 36 + (c4 + 4) * 4];
            aH[3] = *(const float4*)&aHp[(rb + 8) * 36 + (c4 + 4) * 4];
            aL[0] = *(const float4*)&aLp[rb * 36 + c4 * 4];
            aL[1] = *(const float4*)&aLp[(rb + 8) * 36 + c4 * 4];
            aL[2] = *(const float4*)&aLp[rb * 36 + (c4 + 4) * 4];
            aL[3] = *(const float4*)&aLp[(rb + 8) * 36 + (c4 + 4) * 4];
            #pragma unroll
            for (int kt = 0; kt < 4; kt++) {
                float ah0 = ((const float*)&aH[0])[kt], ah1 = ((const float*)&aH[1])[kt];
                float ah2 = ((const float*)&aH[2])[kt], ah3 = ((const float*)&aH[3])[kt];
                float al0 = ((const float*)&aL[0])[kt], al1 = ((const float*)&aL[1])[kt];
                float al2 = ((const float*)&aL[2])[kt], al3 = ((const float*)&aL[3])[kt];
                #pragma unroll
                for (int nt = 0; nt < 2; nt++) {
                    float bh0 = ((const float*)&bH0[nt])[kt], bh1 = ((const float*)&bH1[nt])[kt];
                    mma_tf32(acc[mt][nt], fu(ah0), fu(ah1), fu(ah2), fu(ah3), fu(bh0), fu(bh1));
                    mma_tf32(acc[mt][nt], fu(al0), fu(al1), fu(al2), fu(al3), fu(bh0), fu(bh1));
                }
            }
        }
        if (ck + 1 < nch) store_chunk(1 - p);
        __syncthreads();
    }

    bool left = (n0 < nsplit);
    float* Cb = left ? (C1 + n0) : (C2 + (n0 - nsplit));
    int ldc = left ? ldc1 : ldc2;

    #pragma unroll
    for (int mt = 0; mt < 2; mt++) {
        #pragma unroll
        for (int nt = 0; nt < 2; nt++) {
            int row = m0 + wm * 32 + mt * 16 + r;
            int col = wn * 16 + nt * 8 + 2 * c4;
            float2 bb = *(const float2*)(bias + n0 + col);
            float o0 = acc[mt][nt][0] + bb.x, o1 = acc[mt][nt][1] + bb.y;
            float o2 = acc[mt][nt][2] + bb.x, o3 = acc[mt][nt][3] + bb.y;
            if (RELU) {
                o0 = fmaxf(o0, 0.f); o1 = fmaxf(o1, 0.f);
                o2 = fmaxf(o2, 0.f); o3 = fmaxf(o3, 0.f);
            }
            *(float2*)(Cb + (size_t)row * ldc + col) = make_float2(o0, o1);
            *(float2*)(Cb + (size_t)(row + 8) * ldc + col) = make_float2(o2, o3);
        }
    }
}

// ---------------------------------------------------------------------------
// Attention. Block = (32 i-rows, head, batch), grid (32,4,2).
// s[i,j] = kdot[i] + qdot[j] + sum_a |hk[i,a]+hq[j,a]| * Wa2[a]/2  (exact id).
// hk in REGISTERS (loop-invariant). Thread = (i=lane, 4 j's per warp) so all
// score hq loads are warp-broadcast LDS. wv: 2-pass tf32 mma (w split hi/lo
// exact, v rounded once). Double-buffered hq/v; 2 syncs/iter.
// smem: vH[2][32][136] f32 (34816) | hq[2][32][36] (9216) | wH (4608) |
//       wL (4608) | wa2p[16] ull (128)  = 53376 B
// ---------------------------------------------------------------------------
#define ATTN_SMEM 53376

__global__ __launch_bounds__(256, 2) void attn_kernel(
    const float* __restrict__ hkq,
    const float* __restrict__ dots,
    float* __restrict__ cbuf,
    const float* __restrict__ Wa2)
{
    extern __shared__ char smem[];
    float* vH   = (float*)smem;               // [2][32][136]
    float* hq_s = (float*)(smem + 34816);     // [2][32][36]
    float* wH   = (float*)(smem + 44032);     // [32][36]
    float* wL   = (float*)(smem + 48640);     // [32][36]
    ull*   wa2p = (ull*)(smem + 53248);       // [16]

    int tid = threadIdx.x;
    int lane = tid & 31, w = tid >> 5;
    int it = blockIdx.x, head = blockIdx.y, bb = blockIdx.z;
    int mbase = bb * 1024 + it * 32;
    int w4 = w * 4;

    if (tid < 16) {
        float a0 = 0.5f * Wa2[2 * tid], a1 = 0.5f * Wa2[2 * tid + 1];
        wa2p[tid] = pack2(a0, a1);
    }
    // hk row for this thread -> registers (loop-invariant)
    ull kp[8][2];
    {
        const float* kr = hkq + (size_t)(mbase + lane) * 256 + head * 32;
        #pragma unroll
        for (int a4 = 0; a4 < 8; a4++) {
            float4 f = *(const float4*)(kr + a4 * 4);
            kp[a4][0] = pack2(f.x, f.y);
            kp[a4][1] = pack2(f.z, f.w);
        }
    }
    float ki_dot = dots[(size_t)(mbase + lane) * 8 + head];

    {   // jt=0 tiles -> buffer 0 (hq: 32 j x 8 a4-groups; v: 32 j x 128 d)
        float4 f = *(const float4*)(hkq + (size_t)(bb * 1024 + lane) * 256 + 128 + head * 32 + w * 4);
        *(float4*)&hq_s[lane * 36 + w * 4] = f;
        #pragma unroll
        for (int s = 0; s < 4; s++) {
            int lin = tid + s * 256;
            int jj = lin >> 5, d4 = lin & 31;
            float4 g = *(const float4*)(cbuf + (size_t)(bb * 1024 + jj) * 640 + d4 * 4);
            float4 h;
            h.x = rna_tf32(g.x); h.y = rna_tf32(g.y);
            h.z = rna_tf32(g.z); h.w = rna_tf32(g.w);
            *(float4*)&vH[jj * 136 + d4 * 4] = h;
        }
    }
    __syncthreads();

    float acc[2][2][4];
    #pragma unroll
    for (int i = 0; i < 2; i++)
        #pragma unroll
        for (int j = 0; j < 2; j++)
            #pragma unroll
            for (int e = 0; e < 4; e++) acc[i][j][e] = 0.f;

    const ull ABSM = 0x7FFFFFFF7FFFFFFFULL;
    int gi = it * 32 + lane;   // batch-local i

    for (int jt = 0; jt < 32; jt++) {
        int p = jt & 1;
        const float* vHp = vH + p * 4352;
        const float* hqp = hq_s + p * 1152;
        int jbase = bb * 1024 + jt * 32;

        // q-dots for this tile (L1-resident; used after the score loop)
        float qd[4];
        #pragma unroll
        for (int jj = 0; jj < 4; jj++)
            qd[jj] = dots[(size_t)(jbase + w4 + jj) * 8 + 4 + head];

        // prefetch next tiles into regs
        float4 nhq; float4 nv[4];
        if (jt < 31) {
            int jn = jbase + 32;
            nhq = *(const float4*)(hkq + (size_t)(jn + lane) * 256 + 128 + head * 32 + w * 4);
            #pragma unroll
            for (int s = 0; s < 4; s++) {
                int lin = tid + s * 256;
                nv[s] = *(const float4*)(cbuf + (size_t)(jn + (lin >> 5)) * 640 + (lin & 31) * 4);
            }
        }

        // ---- scores: accumulate sum_a |k+q| * w/2  (4 j's per thread)
        ull s2[4][2];
        #pragma unroll
        for (int jj = 0; jj < 4; jj++) { s2[jj][0] = 0ULL; s2[jj][1] = 0ULL; }
        #pragma unroll
        for (int a4 = 0; a4 < 8; a4++) {
            ull wh0 = wa2p[a4 * 2], wh1 = wa2p[a4 * 2 + 1];
            ull k0 = kp[a4][0], k1 = kp[a4][1];
            #pragma unroll
            for (int jj = 0; jj < 4; jj++) {
                float4 qf = *(const float4*)&hqp[(w4 + jj) * 36 + a4 * 4];  // broadcast
                ull u0 = add2(k0, pack2(qf.x, qf.y));
                ull u1 = add2(k1, pack2(qf.z, qf.w));
                s2[jj][0] = fma2(u0 & ABSM, wh0, s2[jj][0]);
                s2[jj][1] = fma2(u1 & ABSM, wh1, s2[jj][1]);
            }
        }
        float wv[4];
        #pragma unroll
        for (int jj = 0; jj < 4; jj++) {
            float f0, f1, f2, f3;
            unpack2(s2[jj][0], f0, f1);
            unpack2(s2[jj][1], f2, f3);
            float s = ki_dot + qd[jj] + ((f0 + f1) + (f2 + f3));
            if (jt * 32 + w4 + jj == gi) s -= 10000.f;
            wv[jj] = sigmoid_fma(s);
        }
        __syncthreads();   // prev mma done reading wH/wL before overwrite

        // store w split hi/lo at permuted column (row = i = lane)
        #pragma unroll
        for (int jj = 0; jj < 4; jj++) {
            int j = w4 + jj;
            int pj = ((j & 7) << 2) | (j >> 3);
            float h = rna_tf32(wv[jj]);
            wH[lane * 36 + pj] = h;
            wL[lane * 36 + pj] = wv[jj] - h;
        }
        // store prefetched tiles into buffers [1-p]
        if (jt < 31) {
            float* vHn = vH + (1 - p) * 4352;
            float* hqn = hq_s + (1 - p) * 1152;
            *(float4*)&hqn[lane * 36 + w * 4] = nhq;
            #pragma unroll
            for (int s = 0; s < 4; s++) {
                int lin = tid + s * 256;
                int jj = lin >> 5, d4 = lin & 31;
                float4 g = nv[s];
                float4 h;
                h.x = rna_tf32(g.x); h.y = rna_tf32(g.y);
                h.z = rna_tf32(g.z); h.w = rna_tf32(g.w);
                *(float4*)&vHn[jj * 136 + d4 * 4] = h;
            }
        }
        __syncthreads();   // wH/wL + v[p] ready

        // ---- wv mma, 2 passes: (wH + wL) x vH. warp w owns d-cols [w*16, +16)
        {
            int r = lane >> 2, c4 = lane & 3;
            int n0 = w * 16;
            float4 aH[4], aL[4], aH2[4], aL2[4];
            #pragma unroll
            for (int mt = 0; mt < 2; mt++) {
                aH[mt * 2 + 0]  = *(const float4*)&wH[(mt * 16 + r) * 36 + c4 * 4];
                aH[mt * 2 + 1]  = *(const float4*)&wH[(mt * 16 + 8 + r) * 36 + c4 * 4];
                aL[mt * 2 + 0]  = *(const float4*)&wL[(mt * 16 + r) * 36 + c4 * 4];
                aL[mt * 2 + 1]  = *(const float4*)&wL[(mt * 16 + 8 + r) * 36 + c4 * 4];
                aH2[mt * 2 + 0] = *(const float4*)&wH[(mt * 16 + r) * 36 + (c4 + 4) * 4];
                aH2[mt * 2 + 1] = *(const float4*)&wH[(mt * 16 + 8 + r) * 36 + (c4 + 4) * 4];
                aL2[mt * 2 + 0] = *(const float4*)&wL[(mt * 16 + r) * 36 + (c4 + 4) * 4];
                aL2[mt * 2 + 1] = *(const float4*)&wL[(mt * 16 + 8 + r) * 36 + (c4 + 4) * 4];
            }
            #pragma unroll
            for (int kt = 0; kt < 4; kt++) {
                #pragma unroll
                for (int nt = 0; nt < 2; nt++) {
                    int col = n0 + nt * 8 + r;
                    float bh0 = vHp[(kt * 8 + c4) * 136 + col];
                    float bh1 = vHp[(kt * 8 + c4 + 4) * 136 + col];
                    #pragma unroll
                    for (int mt = 0; mt < 2; mt++) {
                        float h0 = ((const float*)&aH[mt * 2 + 0])[kt];
                        float h1 = ((const float*)&aH[mt * 2 + 1])[kt];
                        float h2 = ((const float*)&aH2[mt * 2 + 0])[kt];
                        float h3 = ((const float*)&aH2[mt * 2 + 1])[kt];
                        float l0 = ((const float*)&aL[mt * 2 + 0])[kt];
                        float l1 = ((const float*)&aL[mt * 2 + 1])[kt];
                        float l2 = ((const float*)&aL2[mt * 2 + 0])[kt];
                        float l3 = ((const float*)&aL2[mt * 2 + 1])[kt];
                        mma_tf32(acc[mt][nt], fu(h0), fu(h1), fu(h2), fu(h3), fu(bh0), fu(bh1));
                        mma_tf32(acc[mt][nt], fu(l0), fu(l1), fu(l2), fu(l3), fu(bh0), fu(bh1));
                    }
                }
            }
        }
    }

    // epilogue: fp32 out
    {
        int r = lane >> 2, c4 = lane & 3;
        #pragma unroll
        for (int mt = 0; mt < 2; mt++) {
            #pragma unroll
            for (int nt = 0; nt < 2; nt++) {
                int row = mbase + mt * 16 + r;
                int col = 128 + head * 128 + w * 16 + nt * 8 + 2 * c4;
                *(float2*)(cbuf + (size_t)row * 640 + col) =
                    make_float2(acc[mt][nt][0], acc[mt][nt][1]);
                *(float2*)(cbuf + (size_t)(row + 8) * 640 + col) =
                    make_float2(acc[mt][nt][2], acc[mt][nt][3]);
            }
        }
    }
}

// ---------------------------------------------------------------------------
// launch
// ---------------------------------------------------------------------------
extern "C" void kernel_launch(void* const* d_in, const int* in_sizes, int n_in,
                              void* d_out, int out_size)
{
    const float* x   = (const float*)d_in[0];
    const float* Wk  = (const float*)d_in[1];
    const float* bk  = (const float*)d_in[2];
    const float* Wq  = (const float*)d_in[3];
    const float* bq  = (const float*)d_in[4];
    const float* Wv  = (const float*)d_in[5];
    const float* bv  = (const float*)d_in[6];
    const float* Wa1 = (const float*)d_in[7];
    const float* ba1 = (const float*)d_in[8];
    const float* Wa2 = (const float*)d_in[9];
    const float* ba2 = (const float*)d_in[10];
    const float* Wd1 = (const float*)d_in[11];
    const float* bd1 = (const float*)d_in[12];
    const float* Wd2 = (const float*)d_in[13];
    const float* bd2 = (const float*)d_in[14];
    float* out = (float*)d_out;

    float *pWall, *pball, *phkq, *pdots, *pc, *ph1;
    cudaGetSymbolAddress((void**)&pWall, g_Wall);
    cudaGetSymbolAddress((void**)&pball, g_ball);
    cudaGetSymbolAddress((void**)&phkq, g_hkq);
    cudaGetSymbolAddress((void**)&pdots, g_dots);
    cudaGetSymbolAddress((void**)&pc,   g_c);
    cudaGetSymbolAddress((void**)&ph1,  g_h1);

    cudaFuncSetAttribute(attn_kernel,
                         cudaFuncAttributeMaxDynamicSharedMemorySize, ATTN_SMEM);
    cudaFuncSetAttribute(gemm2x<false>,
                         cudaFuncAttributeMaxDynamicSharedMemorySize, GEMM_SMEM);
    cudaFuncSetAttribute(gemm2x<true>,
                         cudaFuncAttributeMaxDynamicSharedMemorySize, GEMM_SMEM);

    // 1. fused effective weights + biases
    prep_kernel<<<16, 256>>>(Wk, bk, Wq, bq, Wv, bv, Wa1, ba1);

    // 2. [hk|hq|v] = x @ Wall + ball   (M=2048, N=384, K=128)
    gemm2x<false><<<dim3(6, 32), 256, GEMM_SMEM>>>(x, 128, pWall, 384, pball,
                                                   phkq, 256, pc, 640, 256, 128);

    // 3. per-(row,head) score dots
    dots_kernel<<<64, 256>>>(phkq, Wa2, ba2);

    // 4. attention: writes g_c cols [128, 640)
    attn_kernel<<<dim3(32, 4, 2), 256, ATTN_SMEM>>>(phkq, pdots, pc, Wa2);

    // 5. h1 = relu(c @ Wd1 + bd1)      (M=2048, N=256, K=640)
    gemm2x<true><<<dim3(4, 32), 256, GEMM_SMEM>>>(pc, 640, Wd1, 256, bd1,
                                                  ph1, 256, ph1, 256, 1 << 30, 640);

    // 6. out = h1 @ Wd2 + bd2          (M=2048, N=128, K=256)
    gemm2x<false><<<dim3(2, 32), 256, GEMM_SMEM>>>(ph1, 256, Wd2, 128, bd2,
                                                   out, 128, out, 128, 1 << 30, 256);
}

// round 8
// speedup vs baseline: 1.2729x; 1.1282x over previous
#include <cuda_runtime.h>
#include <stdint.h>

typedef unsigned long long ull;

// ---------------------------------------------------------------------------
// Scratch (device globals — no allocation allowed)
// ---------------------------------------------------------------------------
__device__ float g_Wall[128 * 384];   // [Uk | Uq | Wv] fp32
__device__ float g_ball[384];         // [ck+ba1 | cq | bv]
__device__ float g_hkq[2048 * 256];   // [hk | hq]
__device__ float g_dots[2048 * 8];    // per row: [kdot h0..h3 (incl ba2) | qdot h0..h3]
__device__ float g_w[8 * 1024 * 1024];// attention weights per (b,h)
__device__ float g_c[2048 * 640];     // [v | o0..o3] fp32
__device__ float g_h1[2048 * 256];    // decoder hidden fp32

// ---------------------------------------------------------------------------
// helpers
// ---------------------------------------------------------------------------
__device__ __forceinline__ ull pack2(float lo, float hi) {
    ull r; asm("mov.b64 %0, {%1, %2};" : "=l"(r) : "f"(lo), "f"(hi)); return r;
}
__device__ __forceinline__ void unpack2(ull v, float& lo, float& hi) {
    asm("mov.b64 {%0, %1}, %2;" : "=f"(lo), "=f"(hi) : "l"(v));
}
__device__ __forceinline__ ull fma2(ull a, ull b, ull c) {
    ull d; asm("fma.rn.f32x2 %0, %1, %2, %3;" : "=l"(d) : "l"(a), "l"(b), "l"(c)); return d;
}
__device__ __forceinline__ ull add2(ull a, ull b) {
    ull d; asm("add.rn.f32x2 %0, %1, %2;" : "=l"(d) : "l"(a), "l"(b)); return d;
}
__device__ __forceinline__ float rna_tf32(float x) {
    uint32_t r; asm("cvt.rna.tf32.f32 %0, %1;" : "=r"(r) : "f"(x));
    return __uint_as_float(r);
}
__device__ __forceinline__ void mma_tf32(float c[4],
    uint32_t a0, uint32_t a1, uint32_t a2, uint32_t a3,
    uint32_t b0, uint32_t b1)
{
    asm("mma.sync.aligned.m16n8k8.row.col.f32.tf32.tf32.f32 "
        "{%0,%1,%2,%3},{%4,%5,%6,%7},{%8,%9},{%0,%1,%2,%3};"
        : "+f"(c[0]), "+f"(c[1]), "+f"(c[2]), "+f"(c[3])
        : "r"(a0), "r"(a1), "r"(a2), "r"(a3), "r"(b0), "r"(b1));
}
__device__ __forceinline__ uint32_t fu(float x) { return __float_as_uint(x); }

// MUFU-free sigmoid (2 Newton iters on d in (1,2], rel err ~1e-5).
__device__ __forceinline__ float sigmoid_fma(float s) {
    float t = s * 1.4426950408889634f;
    float tn = -fabsf(t);
    tn = fmaxf(tn, -125.0f);
    float m = tn + 12582912.0f;
    int ib = __float_as_int(m);
    float n = m - 12582912.0f;
    float f = tn - n;
    float p = 1.33335581e-3f;
    p = fmaf(p, f, 9.61812910e-3f);
    p = fmaf(p, f, 5.55041087e-2f);
    p = fmaf(p, f, 2.40226507e-1f);
    p = fmaf(p, f, 6.93147181e-1f);
    p = fmaf(p, f, 1.0f);
    float scale = __int_as_float((ib - 0x4B400000 + 127) << 23);
    float e = p * scale;                     // exp(-|s|) in (0,1]
    float d = 1.0f + e;                      // in (1,2]
    float r = fmaf(d, -0.47058824f, 1.41176471f);
    r = r * fmaf(-d, r, 2.0f);
    r = r * fmaf(-d, r, 2.0f);
    float sn = e * r;
    return (s > 0.0f) ? (1.0f - sn) : sn;
}

// ---------------------------------------------------------------------------
// prep: fused [Uk|Uq|Wv] (fp32) + fused bias (ba1 folded into hk bias).
// ---------------------------------------------------------------------------
__global__ __launch_bounds__(256) void prep_kernel(
    const float* __restrict__ Wk, const float* __restrict__ bk,
    const float* __restrict__ Wq, const float* __restrict__ bq,
    const float* __restrict__ Wv, const float* __restrict__ bv,
    const float* __restrict__ Wa1, const float* __restrict__ ba1)
{
    __shared__ float wa[64 * 32];
    int tid = threadIdx.x;
    for (int i = tid; i < 64 * 32; i += 256) wa[i] = Wa1[i];
    __syncthreads();

    int stride = gridDim.x * 256;
    for (int idx = blockIdx.x * 256 + tid; idx < 128 * 128; idx += stride) {
        int d = idx >> 7, j = idx & 127;
        int hb = j & ~31, a = j & 31;
        float sk = 0.f, sq = 0.f;
        #pragma unroll
        for (int t = 0; t < 32; t++) {
            sk += Wk[d * 128 + hb + t] * wa[t * 32 + a];
            sq += Wq[d * 128 + hb + t] * wa[(32 + t) * 32 + a];
        }
        g_Wall[d * 384 + j]       = sk;
        g_Wall[d * 384 + 128 + j] = sq;
        g_Wall[d * 384 + 256 + j] = Wv[d * 128 + j];
    }
    if (blockIdx.x == 0 && tid < 128) {
        int hb = tid & ~31, a = tid & 31;
        float sk = 0.f, sq = 0.f;
        #pragma unroll
        for (int t = 0; t < 32; t++) {
            sk += bk[hb + t] * wa[t * 32 + a];
            sq += bq[hb + t] * wa[(32 + t) * 32 + a];
        }
        g_ball[tid]       = sk + ba1[a];
        g_ball[128 + tid] = sq;
        g_ball[256 + tid] = bv[tid];
    }
}

// ---------------------------------------------------------------------------
// dots: per (row, head): kdot = ba2 + sum_a hk[row,h,a]*Wa2[a]/2
//                        qdot =       sum_a hq[row,h,a]*Wa2[a]/2
// ---------------------------------------------------------------------------
__global__ __launch_bounds__(256) void dots_kernel(
    const float* __restrict__ hkq, const float* __restrict__ Wa2,
    const float* __restrict__ ba2)
{
    int idx = blockIdx.x * 256 + threadIdx.x;   // 2048*8
    if (idx >= 2048 * 8) return;
    int row = idx >> 3, r = idx & 7;
    int isq = r >> 2, h = r & 3;
    const float* base = hkq + (size_t)row * 256 + isq * 128 + h * 32;
    float s = 0.f;
    #pragma unroll
    for (int a = 0; a < 32; a++) s += base[a] * (0.5f * Wa2[a]);
    if (!isq) s += ba2[0];
    g_dots[idx] = s;
}

// ---------------------------------------------------------------------------
// score: w[bh][i][j] = sigmoid(kdot[i] + qdot[j] + sum_a |hk+hq|*Wa2/2 - mask)
// block = 256 thr: warp w covers 32 j's (lane=j), 32 i's per block.
// q-row + Wa2/2 in registers; k broadcast from smem as ull2; coalesced STG.
// grid (4 j-tiles of 256, 32 i-tiles, 8 bh)
// ---------------------------------------------------------------------------
__global__ __launch_bounds__(256, 3) void score_kernel(
    const float* __restrict__ hkq, const float* __restrict__ dots,
    float* __restrict__ wbuf, const float* __restrict__ Wa2)
{
    __shared__ float hk_s[32 * 36];
    __shared__ float kdot_s[32];

    int tid = threadIdx.x;
    int lane = tid & 31, w = tid >> 5;
    int jt = blockIdx.x, itile = blockIdx.y, bh = blockIdx.z;
    int b = bh >> 2, h = bh & 3;
    int ibase = itile * 32;
    int jloc = jt * 256 + w * 32 + lane;
    size_t brow = (size_t)b * 1024;

    {   // hk tile: 32 rows x 32 a
        int row = tid >> 3, g = tid & 7;
        float4 f = *(const float4*)(hkq + (brow + ibase + row) * 256 + h * 32 + g * 4);
        *(float4*)&hk_s[row * 36 + g * 4] = f;
    }
    if (tid < 32) kdot_s[tid] = dots[(brow + ibase + tid) * 8 + h];

    ull qp[8][2];
    {
        const float* qr = hkq + (brow + jloc) * 256 + 128 + h * 32;
        #pragma unroll
        for (int a4 = 0; a4 < 8; a4++) {
            ulonglong2 u = *(const ulonglong2*)(qr + a4 * 4);
            qp[a4][0] = u.x; qp[a4][1] = u.y;
        }
    }
    ull wp[8][2];
    #pragma unroll
    for (int a4 = 0; a4 < 8; a4++) {
        float4 f = *(const float4*)(Wa2 + a4 * 4);
        wp[a4][0] = pack2(0.5f * f.x, 0.5f * f.y);
        wp[a4][1] = pack2(0.5f * f.z, 0.5f * f.w);
    }
    float qd = dots[(brow + jloc) * 8 + 4 + h];
    __syncthreads();

    const ull ABSM = 0x7FFFFFFF7FFFFFFFULL;
    float* wcol = wbuf + ((size_t)bh << 20) + jloc;

    #pragma unroll 4
    for (int i = 0; i < 32; i++) {
        ull s0 = 0ULL, s1 = 0ULL;
        #pragma unroll
        for (int a4 = 0; a4 < 8; a4++) {
            ulonglong2 k = *(const ulonglong2*)&hk_s[i * 36 + a4 * 4];  // broadcast
            ull u0 = add2(k.x, qp[a4][0]);
            ull u1 = add2(k.y, qp[a4][1]);
            s0 = fma2(u0 & ABSM, wp[a4][0], s0);
            s1 = fma2(u1 & ABSM, wp[a4][1], s1);
        }
        float f0, f1, f2, f3;
        unpack2(s0, f0, f1);
        unpack2(s1, f2, f3);
        float s = kdot_s[i] + qd + ((f0 + f1) + (f2 + f3));
        if (ibase + i == jloc) s -= 10000.f;
        wcol[(size_t)(ibase + i) * 1024] = sigmoid_fma(s);
    }
}

// ---------------------------------------------------------------------------
// 2-pass TF32 GEMM: C = act(A @ W + bias).  A split hi/lo (exact), W rounded
// once.  Tile 64x64, K-chunk 32, double-buffered smem, 1 sync/chunk.
// smem: AsH[2][2304] | AsL[2][2304] | Bs[2][2304] = 55296 B
// ---------------------------------------------------------------------------
#define GEMM_SMEM 55296

template <bool RELU>
__global__ __launch_bounds__(256, 2) void gemm2x(
    const float* __restrict__ A, int lda,
    const float* __restrict__ W, int ldw,
    const float* __restrict__ bias,
    float* __restrict__ C1, int ldc1,
    float* __restrict__ C2, int ldc2, int nsplit,
    int K)
{
    extern __shared__ float sm[];
    float* AsH = sm;
    float* AsL = sm + 4608;
    float* Bs  = sm + 9216;

    int tid = threadIdx.x;
    int lane = tid & 31, wq = tid >> 5;
    int wm = wq >> 2, wn = wq & 3;
    int r = lane >> 2, c4 = lane & 3;
    int m0 = blockIdx.y * 64, n0 = blockIdx.x * 64;

    float acc[2][2][4];
    #pragma unroll
    for (int i = 0; i < 2; i++)
        #pragma unroll
        for (int j = 0; j < 2; j++)
            #pragma unroll
            for (int e = 0; e < 4; e++) acc[i][j][e] = 0.f;

    int nch = K >> 5;

    int am[2], ak0[2], bn[2], bk0[2];
    #pragma unroll
    for (int s = 0; s < 2; s++) {
        int lin = tid + s * 256;
        am[s] = lin >> 3;  ak0[s] = lin & 7;
        bn[s] = lin & 63;  bk0[s] = lin >> 6;
    }

    float rA[2][4], rB[2][4];
    auto ldg_chunk = [&](int kc) {
        #pragma unroll
        for (int s = 0; s < 2; s++)
            #pragma unroll
            for (int u = 0; u < 4; u++) {
                rA[s][u] = A[(size_t)(m0 + am[s]) * lda + kc + ak0[s] + 8 * u];
                rB[s][u] = W[(size_t)(kc + bk0[s] + 8 * u) * ldw + n0 + bn[s]];
            }
    };
    auto store_chunk = [&](int buf) {
        float* aH = AsH + buf * 2304;
        float* aL = AsL + buf * 2304;
        float* bs = Bs  + buf * 2304;
        #pragma unroll
        for (int s = 0; s < 2; s++) {
            float4 h, l;
            h.x = rna_tf32(rA[s][0]); h.y = rna_tf32(rA[s][1]);
            h.z = rna_tf32(rA[s][2]); h.w = rna_tf32(rA[s][3]);
            l.x = rA[s][0] - h.x; l.y = rA[s][1] - h.y;
            l.z = rA[s][2] - h.z; l.w = rA[s][3] - h.w;
            *(float4*)&aH[am[s] * 36 + ak0[s] * 4] = h;
            *(float4*)&aL[am[s] * 36 + ak0[s] * 4] = l;
            float4 b;
            b.x = rna_tf32(rB[s][0]); b.y = rna_tf32(rB[s][1]);
            b.z = rna_tf32(rB[s][2]); b.w = rna_tf32(rB[s][3]);
            *(float4*)&bs[bn[s] * 36 + bk0[s] * 4] = b;
        }
    };

    ldg_chunk(0);
    store_chunk(0);
    __syncthreads();

    for (int ck = 0; ck < nch; ck++) {
        int p = ck & 1;
        if (ck + 1 < nch) ldg_chunk((ck + 1) << 5);

        const float* aHp = AsH + p * 2304;
        const float* aLp = AsL + p * 2304;
        const float* bsp = Bs  + p * 2304;

        float4 bH0[2], bH1[2];
        #pragma unroll
        for (int nt = 0; nt < 2; nt++) {
            int nb = wn * 16 + nt * 8 + r;
            bH0[nt] = *(const float4*)&bsp[nb * 36 + c4 * 4];
            bH1[nt] = *(const float4*)&bsp[nb * 36 + (c4 + 4) * 4];
        }
        #pragma unroll
        for (int mt = 0; mt < 2; mt++) {
            int rb = wm * 32 + mt * 16 + r;
            float4 aH[4], aL[4];
            aH[0] = *(const float4*)&aHp[rb * 36 + c4 * 4];
            aH[1] = *(const float4*)&aHp[(rb + 8) * 36 + c4 * 4];
            aH[2] = *(const float4*)&aHp[rb * 36 + (c4 + 4) * 4];
            aH[3] = *(const float4*)&aHp[(rb + 8) * 36 + (c4 + 4) * 4];
            aL[0] = *(const float4*)&aLp[rb * 36 + c4 * 4];
            aL[1] = *(const float4*)&aLp[(rb + 8) * 36 + c4 * 4];
            aL[2] = *(const float4*)&aLp[rb * 36 + (c4 + 4) * 4];
            aL[3] = *(const float4*)&aLp[(rb + 8) * 36 + (c4 + 4) * 4];
            #pragma unroll
            for (int kt = 0; kt < 4; kt++) {
                float ah0 = ((const float*)&aH[0])[kt], ah1 = ((const float*)&aH[1])[kt];
                float ah2 = ((const float*)&aH[2])[kt], ah3 = ((const float*)&aH[3])[kt];
                float al0 = ((const float*)&aL[0])[kt], al1 = ((const float*)&aL[1])[kt];
                float al2 = ((const float*)&aL[2])[kt], al3 = ((const float*)&aL[3])[kt];
                #pragma unroll
                for (int nt = 0; nt < 2; nt++) {
                    float bh0 = ((const float*)&bH0[nt])[kt], bh1 = ((const float*)&bH1[nt])[kt];
                    mma_tf32(acc[mt][nt], fu(ah0), fu(ah1), fu(ah2), fu(ah3), fu(bh0), fu(bh1));
                    mma_tf32(acc[mt][nt], fu(al0), fu(al1), fu(al2), fu(al3), fu(bh0), fu(bh1));
                }
            }
        }
        if (ck + 1 < nch) store_chunk(1 - p);
        __syncthreads();
    }

    bool left = (n0 < nsplit);
    float* Cb = left ? (C1 + n0) : (C2 + (n0 - nsplit));
    int ldc = left ? ldc1 : ldc2;

    #pragma unroll
    for (int mt = 0; mt < 2; mt++) {
        #pragma unroll
        for (int nt = 0; nt < 2; nt++) {
            int row = m0 + wm * 32 + mt * 16 + r;
            int col = wn * 16 + nt * 8 + 2 * c4;
            float2 bb = *(const float2*)(bias + n0 + col);
            float o0 = acc[mt][nt][0] + bb.x, o1 = acc[mt][nt][1] + bb.y;
            float o2 = acc[mt][nt][2] + bb.x, o3 = acc[mt][nt][3] + bb.y;
            if (RELU) {
                o0 = fmaxf(o0, 0.f); o1 = fmaxf(o1, 0.f);
                o2 = fmaxf(o2, 0.f); o3 = fmaxf(o3, 0.f);
            }
            *(float2*)(Cb + (size_t)row * ldc + col) = make_float2(o0, o1);
            *(float2*)(Cb + (size_t)(row + 8) * ldc + col) = make_float2(o2, o3);
        }
    }
}

// ---------------------------------------------------------------------------
// wv GEMM, batched over (b,h): out[b][:,128+h*128:+128] = w[bh] @ v[b]
// M=1024, N=128, K=1024. Same 2-pass structure (w split exact, v rounded).
// grid (2 n-tiles, 16 m-tiles, 8 bh)
// ---------------------------------------------------------------------------
__global__ __launch_bounds__(256, 2) void wv_gemm(
    const float* __restrict__ wbuf, float* __restrict__ cbuf)
{
    extern __shared__ float sm[];
    float* AsH = sm;
    float* AsL = sm + 4608;
    float* Bs  = sm + 9216;

    int tid = threadIdx.x;
    int lane = tid & 31, wq = tid >> 5;
    int wm = wq >> 2, wn = wq & 3;
    int r = lane >> 2, c4 = lane & 3;
    int m0 = blockIdx.y * 64, n0 = blockIdx.x * 64;
    int bh = blockIdx.z;
    int b = bh >> 2, h = bh & 3;

    const float* A = wbuf + ((size_t)bh << 20);            // lda = 1024
    const float* V = cbuf + (size_t)b * 1024 * 640;        // ldw = 640
    float* C = cbuf + (size_t)b * 1024 * 640 + 128 + h * 128 + n0;  // ldc = 640

    float acc[2][2][4];
    #pragma unroll
    for (int i = 0; i < 2; i++)
        #pragma unroll
        for (int j = 0; j < 2; j++)
            #pragma unroll
            for (int e = 0; e < 4; e++) acc[i][j][e] = 0.f;

    int am[2], ak0[2], bn[2], bk0[2];
    #pragma unroll
    for (int s = 0; s < 2; s++) {
        int lin = tid + s * 256;
        am[s] = lin >> 3;  ak0[s] = lin & 7;
        bn[s] = lin & 63;  bk0[s] = lin >> 6;
    }

    float rA[2][4], rB[2][4];
    auto ldg_chunk = [&](int kc) {
        #pragma unroll
        for (int s = 0; s < 2; s++)
            #pragma unroll
            for (int u = 0; u < 4; u++) {
                rA[s][u] = A[(size_t)(m0 + am[s]) * 1024 + kc + ak0[s] + 8 * u];
                rB[s][u] = V[(size_t)(kc + bk0[s] + 8 * u) * 640 + n0 + bn[s]];
            }
    };
    auto store_chunk = [&](int buf) {
        float* aH = AsH + buf * 2304;
        float* aL = AsL + buf * 2304;
        float* bs = Bs  + buf * 2304;
        #pragma unroll
        for (int s = 0; s < 2; s++) {
            float4 hh, l;
            hh.x = rna_tf32(rA[s][0]); hh.y = rna_tf32(rA[s][1]);
            hh.z = rna_tf32(rA[s][2]); hh.w = rna_tf32(rA[s][3]);
            l.x = rA[s][0] - hh.x; l.y = rA[s][1] - hh.y;
            l.z = rA[s][2] - hh.z; l.w = rA[s][3] - hh.w;
            *(float4*)&aH[am[s] * 36 + ak0[s] * 4] = hh;
            *(float4*)&aL[am[s] * 36 + ak0[s] * 4] = l;
            float4 bb;
            bb.x = rna_tf32(rB[s][0]); bb.y = rna_tf32(rB[s][1]);
            bb.z = rna_tf32(rB[s][2]); bb.w = rna_tf32(rB[s][3]);
            *(float4*)&bs[bn[s] * 36 + bk0[s] * 4] = bb;
        }
    };

    ldg_chunk(0);
    store_chunk(0);
    __syncthreads();

    for (int ck = 0; ck < 32; ck++) {
        int p = ck & 1;
        if (ck + 1 < 32) ldg_chunk((ck + 1) << 5);

        const float* aHp = AsH + p * 2304;
        const float* aLp = AsL + p * 2304;
        const float* bsp = Bs  + p * 2304;

        float4 bH0[2], bH1[2];
        #pragma unroll
        for (int nt = 0; nt < 2; nt++) {
            int nb = wn * 16 + nt * 8 + r;
            bH0[nt] = *(const float4*)&bsp[nb * 36 + c4 * 4];
            bH1[nt] = *(const float4*)&bsp[nb * 36 + (c4 + 4) * 4];
        }
        #pragma unroll
        for (int mt = 0; mt < 2; mt++) {
            int rb = wm * 32 + mt * 16 + r;
            float4 aH[4], aL[4];
            aH[0] = *(const float4*)&aHp[rb * 36 + c4 * 4];
            aH[1] = *(const float4*)&aHp[(rb + 8) * 36 + c4 * 4];
            aH[2] = *(const float4*)&aHp[rb * 36 + (c4 + 4) * 4];
            aH[3] = *(const float4*)&aHp[(rb + 8) * 36 + (c4 + 4) * 4];
            aL[0] = *(const float4*)&aLp[rb * 36 + c4 * 4];
            aL[1] = *(const float4*)&aLp[(rb + 8) * 36 + c4 * 4];
            aL[2] = *(const float4*)&aLp[rb * 36 + (c4 + 4) * 4];
            aL[3] = *(const float4*)&aLp[(rb + 8) * 36 + (c4 + 4) * 4];
            #pragma unroll
            for (int kt = 0; kt < 4; kt++) {
                float ah0 = ((const float*)&aH[0])[kt], ah1 = ((const float*)&aH[1])[kt];
                float ah2 = ((const float*)&aH[2])[kt], ah3 = ((const float*)&aH[3])[kt];
                float al0 = ((const float*)&aL[0])[kt], al1 = ((const float*)&aL[1])[kt];
                float al2 = ((const float*)&aL[2])[kt], al3 = ((const float*)&aL[3])[kt];
                #pragma unroll
                for (int nt = 0; nt < 2; nt++) {
                    float bh0 = ((const float*)&bH0[nt])[kt], bh1 = ((const float*)&bH1[nt])[kt];
                    mma_tf32(acc[mt][nt], fu(ah0), fu(ah1), fu(ah2), fu(ah3), fu(bh0), fu(bh1));
                    mma_tf32(acc[mt][nt], fu(al0), fu(al1), fu(al2), fu(al3), fu(bh0), fu(bh1));
                }
            }
        }
        if (ck + 1 < 32) store_chunk(1 - p);
        __syncthreads();
    }

    #pragma unroll
    for (int mt = 0; mt < 2; mt++) {
        #pragma unroll
        for (int nt = 0; nt < 2; nt++) {
            int row = m0 + wm * 32 + mt * 16 + r;
            int col = wn * 16 + nt * 8 + 2 * c4;
            *(float2*)(C + (size_t)row * 640 + col) =
                make_float2(acc[mt][nt][0], acc[mt][nt][1]);
            *(float2*)(C + (size_t)(row + 8) * 640 + col) =
                make_float2(acc[mt][nt][2], acc[mt][nt][3]);
        }
    }
}

// ---------------------------------------------------------------------------
// launch
// ---------------------------------------------------------------------------
extern "C" void kernel_launch(void* const* d_in, const int* in_sizes, int n_in,
                              void* d_out, int out_size)
{
    const float* x   = (const float*)d_in[0];
    const float* Wk  = (const float*)d_in[1];
    const float* bk  = (const float*)d_in[2];
    const float* Wq  = (const float*)d_in[3];
    const float* bq  = (const float*)d_in[4];
    const float* Wv  = (const float*)d_in[5];
    const float* bv  = (const float*)d_in[6];
    const float* Wa1 = (const float*)d_in[7];
    const float* ba1 = (const float*)d_in[8];
    const float* Wa2 = (const float*)d_in[9];
    const float* ba2 = (const float*)d_in[10];
    const float* Wd1 = (const float*)d_in[11];
    const float* bd1 = (const float*)d_in[12];
    const float* Wd2 = (const float*)d_in[13];
    const float* bd2 = (const float*)d_in[14];
    float* out = (float*)d_out;

    float *pWall, *pball, *phkq, *pdots, *pw, *pc, *ph1;
    cudaGetSymbolAddress((void**)&pWall, g_Wall);
    cudaGetSymbolAddress((void**)&pball, g_ball);
    cudaGetSymbolAddress((void**)&phkq, g_hkq);
    cudaGetSymbolAddress((void**)&pdots, g_dots);
    cudaGetSymbolAddress((void**)&pw,   g_w);
    cudaGetSymbolAddress((void**)&pc,   g_c);
    cudaGetSymbolAddress((void**)&ph1,  g_h1);

    cudaFuncSetAttribute(gemm2x<false>,
                         cudaFuncAttributeMaxDynamicSharedMemorySize, GEMM_SMEM);
    cudaFuncSetAttribute(gemm2x<true>,
                         cudaFuncAttributeMaxDynamicSharedMemorySize, GEMM_SMEM);
    cudaFuncSetAttribute(wv_gemm,
                         cudaFuncAttributeMaxDynamicSharedMemorySize, GEMM_SMEM);

    // 1. fused effective weights + biases
    prep_kernel<<<16, 256>>>(Wk, bk, Wq, bq, Wv, bv, Wa1, ba1);

    // 2. [hk|hq|v] = x @ Wall + ball   (M=2048, N=384, K=128)
    gemm2x<false><<<dim3(6, 32), 256, GEMM_SMEM>>>(x, 128, pWall, 384, pball,
                                                   phkq, 256, pc, 640, 256, 128);

    // 3. per-(row,head) score dots
    dots_kernel<<<64, 256>>>(phkq, Wa2, ba2);

    // 4. attention scores -> g_w
    score_kernel<<<dim3(4, 32, 8), 256>>>(phkq, pdots, pw, Wa2);

    // 5. o = w @ v  -> g_c cols [128,640)
    wv_gemm<<<dim3(2, 16, 8), 256, GEMM_SMEM>>>(pw, pc);

    // 6. h1 = relu(c @ Wd1 + bd1)      (M=2048, N=256, K=640)
    gemm2x<true><<<dim3(4, 32), 256, GEMM_SMEM>>>(pc, 640, Wd1, 256, bd1,
                                                  ph1, 256, ph1, 256, 1 << 30, 640);

    // 7. out = h1 @ Wd2 + bd2          (M=2048, N=128, K=256)
    gemm2x<false><<<dim3(2, 32), 256, GEMM_SMEM>>>(ph1, 256, Wd2, 128, bd2,
                                                   out, 128, out, 128, 1 << 30, 256);
}

// round 9
// speedup vs baseline: 1.3229x; 1.0393x over previous
#include <cuda_runtime.h>
#include <stdint.h>

typedef unsigned long long ull;

// ---------------------------------------------------------------------------
// Scratch (device globals — no allocation allowed)
// ---------------------------------------------------------------------------
__device__ float g_Wall[128 * 384];   // [Uk | Uq | Wv] fp32
__device__ float g_ball[384];         // [ck+ba1 | cq | bv]
__device__ float g_hkq[2048 * 256];   // [hk | hq]
__device__ float g_dots[2048 * 8];    // per row: [kdot h0..h3 (incl ba2) | qdot h0..h3]
__device__ float g_w[8 * 1024 * 1024];// attention weights (tf32-rounded) per (b,h)
__device__ float g_c[2048 * 640];     // [v | o0..o3] fp32
__device__ float g_h1[2048 * 256];    // decoder hidden fp32

// ---------------------------------------------------------------------------
// helpers
// ---------------------------------------------------------------------------
__device__ __forceinline__ ull pack2(float lo, float hi) {
    ull r; asm("mov.b64 %0, {%1, %2};" : "=l"(r) : "f"(lo), "f"(hi)); return r;
}
__device__ __forceinline__ void unpack2(ull v, float& lo, float& hi) {
    asm("mov.b64 {%0, %1}, %2;" : "=f"(lo), "=f"(hi) : "l"(v));
}
__device__ __forceinline__ ull fma2(ull a, ull b, ull c) {
    ull d; asm("fma.rn.f32x2 %0, %1, %2, %3;" : "=l"(d) : "l"(a), "l"(b), "l"(c)); return d;
}
__device__ __forceinline__ ull add2(ull a, ull b) {
    ull d; asm("add.rn.f32x2 %0, %1, %2;" : "=l"(d) : "l"(a), "l"(b)); return d;
}
__device__ __forceinline__ float rna_tf32(float x) {
    uint32_t r; asm("cvt.rna.tf32.f32 %0, %1;" : "=r"(r) : "f"(x));
    return __uint_as_float(r);
}
__device__ __forceinline__ void mma_tf32(float c[4],
    uint32_t a0, uint32_t a1, uint32_t a2, uint32_t a3,
    uint32_t b0, uint32_t b1)
{
    asm("mma.sync.aligned.m16n8k8.row.col.f32.tf32.tf32.f32 "
        "{%0,%1,%2,%3},{%4,%5,%6,%7},{%8,%9},{%0,%1,%2,%3};"
        : "+f"(c[0]), "+f"(c[1]), "+f"(c[2]), "+f"(c[3])
        : "r"(a0), "r"(a1), "r"(a2), "r"(a3), "r"(b0), "r"(b1));
}
__device__ __forceinline__ uint32_t fu(float x) { return __float_as_uint(x); }

// MUFU-free sigmoid (2 Newton iters on d in (1,2], rel err ~1e-5).
__device__ __forceinline__ float sigmoid_fma(float s) {
    float t = s * 1.4426950408889634f;
    float tn = -fabsf(t);
    tn = fmaxf(tn, -125.0f);
    float m = tn + 12582912.0f;
    int ib = __float_as_int(m);
    float n = m - 12582912.0f;
    float f = tn - n;
    float p = 1.33335581e-3f;
    p = fmaf(p, f, 9.61812910e-3f);
    p = fmaf(p, f, 5.55041087e-2f);
    p = fmaf(p, f, 2.40226507e-1f);
    p = fmaf(p, f, 6.93147181e-1f);
    p = fmaf(p, f, 1.0f);
    float scale = __int_as_float((ib - 0x4B400000 + 127) << 23);
    float e = p * scale;
    float d = 1.0f + e;
    float r = fmaf(d, -0.47058824f, 1.41176471f);
    r = r * fmaf(-d, r, 2.0f);
    r = r * fmaf(-d, r, 2.0f);
    float sn = e * r;
    return (s > 0.0f) ? (1.0f - sn) : sn;
}

// ---------------------------------------------------------------------------
// prep: fused [Uk|Uq|Wv] (fp32) + fused bias (ba1 folded into hk bias).
// ---------------------------------------------------------------------------
__global__ __launch_bounds__(256) void prep_kernel(
    const float* __restrict__ Wk, const float* __restrict__ bk,
    const float* __restrict__ Wq, const float* __restrict__ bq,
    const float* __restrict__ Wv, const float* __restrict__ bv,
    const float* __restrict__ Wa1, const float* __restrict__ ba1)
{
    __shared__ float wa[64 * 32];
    int tid = threadIdx.x;
    for (int i = tid; i < 64 * 32; i += 256) wa[i] = Wa1[i];
    __syncthreads();

    int stride = gridDim.x * 256;
    for (int idx = blockIdx.x * 256 + tid; idx < 128 * 128; idx += stride) {
        int d = idx >> 7, j = idx & 127;
        int hb = j & ~31, a = j & 31;
        float sk = 0.f, sq = 0.f;
        #pragma unroll
        for (int t = 0; t < 32; t++) {
            sk += Wk[d * 128 + hb + t] * wa[t * 32 + a];
            sq += Wq[d * 128 + hb + t] * wa[(32 + t) * 32 + a];
        }
        g_Wall[d * 384 + j]       = sk;
        g_Wall[d * 384 + 128 + j] = sq;
        g_Wall[d * 384 + 256 + j] = Wv[d * 128 + j];
    }
    if (blockIdx.x == 0 && tid < 128) {
        int hb = tid & ~31, a = tid & 31;
        float sk = 0.f, sq = 0.f;
        #pragma unroll
        for (int t = 0; t < 32; t++) {
            sk += bk[hb + t] * wa[t * 32 + a];
            sq += bq[hb + t] * wa[(32 + t) * 32 + a];
        }
        g_ball[tid]       = sk + ba1[a];
        g_ball[128 + tid] = sq;
        g_ball[256 + tid] = bv[tid];
    }
}

// ---------------------------------------------------------------------------
// dots: per (row, head): kdot = ba2 + sum_a hk*Wa2/2 ; qdot = sum_a hq*Wa2/2
// ---------------------------------------------------------------------------
__global__ __launch_bounds__(256) void dots_kernel(
    const float* __restrict__ hkq, const float* __restrict__ Wa2,
    const float* __restrict__ ba2)
{
    int idx = blockIdx.x * 256 + threadIdx.x;
    if (idx >= 2048 * 8) return;
    int row = idx >> 3, r = idx & 7;
    int isq = r >> 2, h = r & 3;
    const float* base = hkq + (size_t)row * 256 + isq * 128 + h * 32;
    float s = 0.f;
    #pragma unroll
    for (int a = 0; a < 32; a++) s += base[a] * (0.5f * Wa2[a]);
    if (!isq) s += ba2[0];
    g_dots[idx] = s;
}

// ---------------------------------------------------------------------------
// score: w[bh][i][j] = rna(sigmoid(kdot[i]+qdot[j]+sum_a |hk+hq|*Wa2/2 - mask))
// q-row in registers; Wa2 packs in smem (broadcast LDS, frees 32 regs -> occ 4).
// ---------------------------------------------------------------------------
__global__ __launch_bounds__(256, 4) void score_kernel(
    const float* __restrict__ hkq, const float* __restrict__ dots,
    float* __restrict__ wbuf, const float* __restrict__ Wa2)
{
    __shared__ float hk_s[32 * 36];
    __shared__ float kdot_s[32];
    __shared__ ull wa2s[16];

    int tid = threadIdx.x;
    int lane = tid & 31, w = tid >> 5;
    int jt = blockIdx.x, itile = blockIdx.y, bh = blockIdx.z;
    int b = bh >> 2, h = bh & 3;
    int ibase = itile * 32;
    int jloc = jt * 256 + w * 32 + lane;
    size_t brow = (size_t)b * 1024;

    {   // hk tile: 32 rows x 32 a
        int row = tid >> 3, g = tid & 7;
        float4 f = *(const float4*)(hkq + (brow + ibase + row) * 256 + h * 32 + g * 4);
        *(float4*)&hk_s[row * 36 + g * 4] = f;
    }
    if (tid < 32) kdot_s[tid] = dots[(brow + ibase + tid) * 8 + h];
    if (tid < 16) {
        float a0 = 0.5f * Wa2[2 * tid], a1 = 0.5f * Wa2[2 * tid + 1];
        wa2s[tid] = pack2(a0, a1);
    }

    ull qp[8][2];
    {
        const float* qr = hkq + (brow + jloc) * 256 + 128 + h * 32;
        #pragma unroll
        for (int a4 = 0; a4 < 8; a4++) {
            ulonglong2 u = *(const ulonglong2*)(qr + a4 * 4);
            qp[a4][0] = u.x; qp[a4][1] = u.y;
        }
    }
    float qd = dots[(brow + jloc) * 8 + 4 + h];
    __syncthreads();

    const ull ABSM = 0x7FFFFFFF7FFFFFFFULL;
    float* wcol = wbuf + ((size_t)bh << 20) + jloc;

    #pragma unroll 4
    for (int i = 0; i < 32; i++) {
        ull s0 = 0ULL, s1 = 0ULL;
        #pragma unroll
        for (int a4 = 0; a4 < 8; a4++) {
            ulonglong2 k = *(const ulonglong2*)&hk_s[i * 36 + a4 * 4];  // broadcast
            ulonglong2 wp = *(const ulonglong2*)&wa2s[a4 * 2];          // broadcast
            ull u0 = add2(k.x, qp[a4][0]);
            ull u1 = add2(k.y, qp[a4][1]);
            s0 = fma2(u0 & ABSM, wp.x, s0);
            s1 = fma2(u1 & ABSM, wp.y, s1);
        }
        float f0, f1, f2, f3;
        unpack2(s0, f0, f1);
        unpack2(s1, f2, f3);
        float s = kdot_s[i] + qd + ((f0 + f1) + (f2 + f3));
        if (ibase + i == jloc) s -= 10000.f;
        wcol[(size_t)(ibase + i) * 1024] = rna_tf32(sigmoid_fma(s));
    }
}

// ---------------------------------------------------------------------------
// TF32 GEMM: C = act(A @ W + bias).  SPLIT: A hi/lo (exact), 2 mma passes;
// else single pass with A rounded at STS.  B always rounded at STS.
// Tile 64x64, K-chunk 32, double-buffered smem, 1 sync/chunk.
// smem: SPLIT: AsH[2][2304]|AsL[2][2304]|Bs[2][2304]=55296; else 36864.
// ---------------------------------------------------------------------------
#define GEMM_SMEM_SPLIT 55296
#define GEMM_SMEM_1X    36864

template <bool RELU, bool SPLIT>
__global__ __launch_bounds__(256, SPLIT ? 2 : 3) void gemm_k(
    const float* __restrict__ A, int lda,
    const float* __restrict__ W, int ldw,
    const float* __restrict__ bias,
    float* __restrict__ C1, int ldc1,
    float* __restrict__ C2, int ldc2, int nsplit,
    int K)
{
    extern __shared__ float sm[];
    float* AsH = sm;
    float* AsL = SPLIT ? sm + 4608 : sm;
    float* Bs  = sm + (SPLIT ? 9216 : 4608);

    int tid = threadIdx.x;
    int lane = tid & 31, wq = tid >> 5;
    int wm = wq >> 2, wn = wq & 3;
    int r = lane >> 2, c4 = lane & 3;
    int m0 = blockIdx.y * 64, n0 = blockIdx.x * 64;

    float acc[2][2][4];
    #pragma unroll
    for (int i = 0; i < 2; i++)
        #pragma unroll
        for (int j = 0; j < 2; j++)
            #pragma unroll
            for (int e = 0; e < 4; e++) acc[i][j][e] = 0.f;

    int nch = K >> 5;

    int am[2], ak0[2], bn[2], bk0[2];
    #pragma unroll
    for (int s = 0; s < 2; s++) {
        int lin = tid + s * 256;
        am[s] = lin >> 3;  ak0[s] = lin & 7;
        bn[s] = lin & 63;  bk0[s] = lin >> 6;
    }

    float rA[2][4], rB[2][4];
    auto ldg_chunk = [&](int kc) {
        #pragma unroll
        for (int s = 0; s < 2; s++)
            #pragma unroll
            for (int u = 0; u < 4; u++) {
                rA[s][u] = A[(size_t)(m0 + am[s]) * lda + kc + ak0[s] + 8 * u];
                rB[s][u] = W[(size_t)(kc + bk0[s] + 8 * u) * ldw + n0 + bn[s]];
            }
    };
    auto store_chunk = [&](int buf) {
        float* aH = AsH + buf * 2304;
        float* bs = Bs  + buf * 2304;
        #pragma unroll
        for (int s = 0; s < 2; s++) {
            float4 h;
            h.x = rna_tf32(rA[s][0]); h.y = rna_tf32(rA[s][1]);
            h.z = rna_tf32(rA[s][2]); h.w = rna_tf32(rA[s][3]);
            *(float4*)&aH[am[s] * 36 + ak0[s] * 4] = h;
            if (SPLIT) {
                float* aL = AsL + buf * 2304;
                float4 l;
                l.x = rA[s][0] - h.x; l.y = rA[s][1] - h.y;
                l.z = rA[s][2] - h.z; l.w = rA[s][3] - h.w;
                *(float4*)&aL[am[s] * 36 + ak0[s] * 4] = l;
            }
            float4 b;
            b.x = rna_tf32(rB[s][0]); b.y = rna_tf32(rB[s][1]);
            b.z = rna_tf32(rB[s][2]); b.w = rna_tf32(rB[s][3]);
            *(float4*)&bs[bn[s] * 36 + bk0[s] * 4] = b;
        }
    };

    ldg_chunk(0);
    store_chunk(0);
    __syncthreads();

    for (int ck = 0; ck < nch; ck++) {
        int p = ck & 1;
        if (ck + 1 < nch) ldg_chunk((ck + 1) << 5);

        const float* aHp = AsH + p * 2304;
        const float* aLp = AsL + p * 2304;
        const float* bsp = Bs  + p * 2304;

        float4 bH0[2], bH1[2];
        #pragma unroll
        for (int nt = 0; nt < 2; nt++) {
            int nb = wn * 16 + nt * 8 + r;
            bH0[nt] = *(const float4*)&bsp[nb * 36 + c4 * 4];
            bH1[nt] = *(const float4*)&bsp[nb * 36 + (c4 + 4) * 4];
        }
        #pragma unroll
        for (int mt = 0; mt < 2; mt++) {
            int rb = wm * 32 + mt * 16 + r;
            float4 aH[4], aL[4];
            aH[0] = *(const float4*)&aHp[rb * 36 + c4 * 4];
            aH[1] = *(const float4*)&aHp[(rb + 8) * 36 + c4 * 4];
            aH[2] = *(const float4*)&aHp[rb * 36 + (c4 + 4) * 4];
            aH[3] = *(const float4*)&aHp[(rb + 8) * 36 + (c4 + 4) * 4];
            if (SPLIT) {
                aL[0] = *(const float4*)&aLp[rb * 36 + c4 * 4];
                aL[1] = *(const float4*)&aLp[(rb + 8) * 36 + c4 * 4];
                aL[2] = *(const float4*)&aLp[rb * 36 + (c4 + 4) * 4];
                aL[3] = *(const float4*)&aLp[(rb + 8) * 36 + (c4 + 4) * 4];
            }
            #pragma unroll
            for (int kt = 0; kt < 4; kt++) {
                float ah0 = ((const float*)&aH[0])[kt], ah1 = ((const float*)&aH[1])[kt];
                float ah2 = ((const float*)&aH[2])[kt], ah3 = ((const float*)&aH[3])[kt];
                #pragma unroll
                for (int nt = 0; nt < 2; nt++) {
                    float bh0 = ((const float*)&bH0[nt])[kt], bh1 = ((const float*)&bH1[nt])[kt];
                    mma_tf32(acc[mt][nt], fu(ah0), fu(ah1), fu(ah2), fu(ah3), fu(bh0), fu(bh1));
                    if (SPLIT) {
                        float al0 = ((const float*)&aL[0])[kt], al1 = ((const float*)&aL[1])[kt];
                        float al2 = ((const float*)&aL[2])[kt], al3 = ((const float*)&aL[3])[kt];
                        mma_tf32(acc[mt][nt], fu(al0), fu(al1), fu(al2), fu(al3), fu(bh0), fu(bh1));
                    }
                }
            }
        }
        if (ck + 1 < nch) store_chunk(1 - p);
        __syncthreads();
    }

    bool left = (n0 < nsplit);
    float* Cb = left ? (C1 + n0) : (C2 + (n0 - nsplit));
    int ldc = left ? ldc1 : ldc2;

    #pragma unroll
    for (int mt = 0; mt < 2; mt++) {
        #pragma unroll
        for (int nt = 0; nt < 2; nt++) {
            int row = m0 + wm * 32 + mt * 16 + r;
            int col = wn * 16 + nt * 8 + 2 * c4;
            float2 bb = *(const float2*)(bias + n0 + col);
            float o0 = acc[mt][nt][0] + bb.x, o1 = acc[mt][nt][1] + bb.y;
            float o2 = acc[mt][nt][2] + bb.x, o3 = acc[mt][nt][3] + bb.y;
            if (RELU) {
                o0 = fmaxf(o0, 0.f); o1 = fmaxf(o1, 0.f);
                o2 = fmaxf(o2, 0.f); o3 = fmaxf(o3, 0.f);
            }
            *(float2*)(Cb + (size_t)row * ldc + col) = make_float2(o0, o1);
            *(float2*)(Cb + (size_t)(row + 8) * ldc + col) = make_float2(o2, o3);
        }
    }
}

// ---------------------------------------------------------------------------
// wv GEMM, batched over (b,h): out[b][:,128+h*128:+128] = w[bh] @ v[b]
// Single-pass tf32: w pre-rounded (stored rounded by score), v rounded at STS.
// grid (2 n-tiles, 16 m-tiles, 8 bh)
// ---------------------------------------------------------------------------
__global__ __launch_bounds__(256, 3) void wv_gemm(
    const float* __restrict__ wbuf, float* __restrict__ cbuf)
{
    extern __shared__ float sm[];
    float* As = sm;
    float* Bs = sm + 4608;

    int tid = threadIdx.x;
    int lane = tid & 31, wq = tid >> 5;
    int wm = wq >> 2, wn = wq & 3;
    int r = lane >> 2, c4 = lane & 3;
    int m0 = blockIdx.y * 64, n0 = blockIdx.x * 64;
    int bh = blockIdx.z;
    int b = bh >> 2, h = bh & 3;

    const float* A = wbuf + ((size_t)bh << 20);            // lda = 1024
    const float* V = cbuf + (size_t)b * 1024 * 640;        // ldw = 640
    float* C = cbuf + (size_t)b * 1024 * 640 + 128 + h * 128 + n0;

    float acc[2][2][4];
    #pragma unroll
    for (int i = 0; i < 2; i++)
        #pragma unroll
        for (int j = 0; j < 2; j++)
            #pragma unroll
            for (int e = 0; e < 4; e++) acc[i][j][e] = 0.f;

    int am[2], ak0[2], bn[2], bk0[2];
    #pragma unroll
    for (int s = 0; s < 2; s++) {
        int lin = tid + s * 256;
        am[s] = lin >> 3;  ak0[s] = lin & 7;
        bn[s] = lin & 63;  bk0[s] = lin >> 6;
    }

    float rA[2][4], rB[2][4];
    auto ldg_chunk = [&](int kc) {
        #pragma unroll
        for (int s = 0; s < 2; s++)
            #pragma unroll
            for (int u = 0; u < 4; u++) {
                rA[s][u] = A[(size_t)(m0 + am[s]) * 1024 + kc + ak0[s] + 8 * u];
                rB[s][u] = V[(size_t)(kc + bk0[s] + 8 * u) * 640 + n0 + bn[s]];
            }
    };
    auto store_chunk = [&](int buf) {
        float* as = As + buf * 2304;
        float* bs = Bs + buf * 2304;
        #pragma unroll
        for (int s = 0; s < 2; s++) {
            float4 a;   // pre-rounded: direct store
            a.x = rA[s][0]; a.y = rA[s][1]; a.z = rA[s][2]; a.w = rA[s][3];
            *(float4*)&as[am[s] * 36 + ak0[s] * 4] = a;
            float4 bb;
            bb.x = rna_tf32(rB[s][0]); bb.y = rna_tf32(rB[s][1]);
            bb.z = rna_tf32(rB[s][2]); bb.w = rna_tf32(rB[s][3]);
            *(float4*)&bs[bn[s] * 36 + bk0[s] * 4] = bb;
        }
    };

    ldg_chunk(0);
    store_chunk(0);
    __syncthreads();

    for (int ck = 0; ck < 32; ck++) {
        int p = ck & 1;
        if (ck + 1 < 32) ldg_chunk((ck + 1) << 5);

        const float* asp = As + p * 2304;
        const float* bsp = Bs + p * 2304;

        float4 bH0[2], bH1[2];
        #pragma unroll
        for (int nt = 0; nt < 2; nt++) {
            int nb = wn * 16 + nt * 8 + r;
            bH0[nt] = *(const float4*)&bsp[nb * 36 + c4 * 4];
            bH1[nt] = *(const float4*)&bsp[nb * 36 + (c4 + 4) * 4];
        }
        #pragma unroll
        for (int mt = 0; mt < 2; mt++) {
            int rb = wm * 32 + mt * 16 + r;
            float4 aH[4];
            aH[0] = *(const float4*)&asp[rb * 36 + c4 * 4];
            aH[1] = *(const float4*)&asp[(rb + 8) * 36 + c4 * 4];
            aH[2] = *(const float4*)&asp[rb * 36 + (c4 + 4) * 4];
            aH[3] = *(const float4*)&asp[(rb + 8) * 36 + (c4 + 4) * 4];
            #pragma unroll
            for (int kt = 0; kt < 4; kt++) {
                float ah0 = ((const float*)&aH[0])[kt], ah1 = ((const float*)&aH[1])[kt];
                float ah2 = ((const float*)&aH[2])[kt], ah3 = ((const float*)&aH[3])[kt];
                #pragma unroll
                for (int nt = 0; nt < 2; nt++) {
                    float bh0 = ((const float*)&bH0[nt])[kt], bh1 = ((const float*)&bH1[nt])[kt];
                    mma_tf32(acc[mt][nt], fu(ah0), fu(ah1), fu(ah2), fu(ah3), fu(bh0), fu(bh1));
                }
            }
        }
        if (ck + 1 < 32) store_chunk(1 - p);
        __syncthreads();
    }

    #pragma unroll
    for (int mt = 0; mt < 2; mt++) {
        #pragma unroll
        for (int nt = 0; nt < 2; nt++) {
            int row = m0 + wm * 32 + mt * 16 + r;
            int col = wn * 16 + nt * 8 + 2 * c4;
            *(float2*)(C + (size_t)row * 640 + col) =
                make_float2(acc[mt][nt][0], acc[mt][nt][1]);
            *(float2*)(C + (size_t)(row + 8) * 640 + col) =
                make_float2(acc[mt][nt][2], acc[mt][nt][3]);
        }
    }
}

// ---------------------------------------------------------------------------
// launch
// ---------------------------------------------------------------------------
extern "C" void kernel_launch(void* const* d_in, const int* in_sizes, int n_in,
                              void* d_out, int out_size)
{
    const float* x   = (const float*)d_in[0];
    const float* Wk  = (const float*)d_in[1];
    const float* bk  = (const float*)d_in[2];
    const float* Wq  = (const float*)d_in[3];
    const float* bq  = (const float*)d_in[4];
    const float* Wv  = (const float*)d_in[5];
    const float* bv  = (const float*)d_in[6];
    const float* Wa1 = (const float*)d_in[7];
    const float* ba1 = (const float*)d_in[8];
    const float* Wa2 = (const float*)d_in[9];
    const float* ba2 = (const float*)d_in[10];
    const float* Wd1 = (const float*)d_in[11];
    const float* bd1 = (const float*)d_in[12];
    const float* Wd2 = (const float*)d_in[13];
    const float* bd2 = (const float*)d_in[14];
    float* out = (float*)d_out;

    float *pWall, *pball, *phkq, *pdots, *pw, *pc, *ph1;
    cudaGetSymbolAddress((void**)&pWall, g_Wall);
    cudaGetSymbolAddress((void**)&pball, g_ball);
    cudaGetSymbolAddress((void**)&phkq, g_hkq);
    cudaGetSymbolAddress((void**)&pdots, g_dots);
    cudaGetSymbolAddress((void**)&pw,   g_w);
    cudaGetSymbolAddress((void**)&pc,   g_c);
    cudaGetSymbolAddress((void**)&ph1,  g_h1);

    cudaFuncSetAttribute((const void*)gemm_k<false, true>,
                         cudaFuncAttributeMaxDynamicSharedMemorySize, GEMM_SMEM_SPLIT);
    cudaFuncSetAttribute((const void*)gemm_k<true, false>,
                         cudaFuncAttributeMaxDynamicSharedMemorySize, GEMM_SMEM_1X);
    cudaFuncSetAttribute((const void*)wv_gemm,
                         cudaFuncAttributeMaxDynamicSharedMemorySize, GEMM_SMEM_1X);

    // 1. fused effective weights + biases
    prep_kernel<<<16, 256>>>(Wk, bk, Wq, bq, Wv, bv, Wa1, ba1);

    // 2. [hk|hq|v] = x @ Wall + ball   (2-pass: exact A)
    gemm_k<false, true><<<dim3(6, 32), 256, GEMM_SMEM_SPLIT>>>(
        x, 128, pWall, 384, pball, phkq, 256, pc, 640, 256, 128);

    // 3. per-(row,head) score dots
    dots_kernel<<<64, 256>>>(phkq, Wa2, ba2);

    // 4. attention scores -> g_w (tf32-rounded)
    score_kernel<<<dim3(4, 32, 8), 256>>>(phkq, pdots, pw, Wa2);

    // 5. o = w @ v  -> g_c cols [128,640)   (single-pass)
    wv_gemm<<<dim3(2, 16, 8), 256, GEMM_SMEM_1X>>>(pw, pc);

    // 6. h1 = relu(c @ Wd1 + bd1)   (single-pass)
    gemm_k<true, false><<<dim3(4, 32), 256, GEMM_SMEM_1X>>>(
        pc, 640, Wd1, 256, bd1, ph1, 256, ph1, 256, 1 << 30, 640);

    // 7. out = h1 @ Wd2 + bd2       (2-pass: exact A, error safety)
    gemm_k<false, true><<<dim3(2, 32), 256, GEMM_SMEM_SPLIT>>>(
        ph1, 256, Wd2, 128, bd2, out, 128, out, 128, 1 << 30, 256);
}